// round 9
// baseline (speedup 1.0000x reference)
#include <cuda_runtime.h>
#include <stdint.h>

// ---------------- problem constants ----------------------------------------
constexpr int cN = 268, cS = 32, cE = 1024, cB = 4;
constexpr float cScale = 0.03125f;           // 1/sqrt(1024)
constexpr size_t MM  = 1024ull * 1024ull;
constexpr int   TNK  = cS * cN;              // 8576
constexpr size_t NE  = (size_t)cN * cE;      // 274432
constexpr size_t SNE = (size_t)TNK * cE;     // 8781824
constexpr int   KCH  = TNK / 4;              // 2144

// ---------------- scratch (device globals) ----------------------------------
__device__ __align__(1024) float g_Wr [10 * MM];   // rounded: wq_b(0-3), wq(4), wk_b(5-8), wk(9)
__device__ __align__(1024) float g_WvT[5 * MM];    // transposed+rounded: wv_b(0-3), wv(4)
__device__ __align__(1024) float g_G  [5 * MM];    // Gt = wk*wq^T per branch + stage2
__device__ __align__(1024) float g_F  [cN * cE];   // rounded features
__device__ __align__(1024) float g_St [4 * SNE];   // rounded transposed snapshots [b][e][tm]
__device__ __align__(1024) float g_qh [5 * NE];    // q-tilde per branch + stage2
__device__ __align__(1024) float g_P  [(size_t)cB * cN * TNK];  // probs [b][n][t*m]
__device__ __align__(1024) float g_UP [16 * NE];   // partials scratch (reused)
__device__ __align__(1024) float g_U  [4 * NE];    // U reduced+rounded
__device__ __align__(1024) float g_ms [4 * NE];    // branch outputs (rounded)
__device__ __align__(1024) float g_MST[(size_t)cE * 4 * cN];    // ms^T [e][tm2]
__device__ __align__(1024) float g_P2 [(size_t)cN * 4 * cN];    // stage2 probs [n][t*m]
__device__ __align__(1024) float g_U2 [NE];        // stage2 U (rounded)

// ---------------- PTX helpers -----------------------------------------------
__device__ __forceinline__ uint32_t smem_u32(const void* p) {
    uint32_t a;
    asm("{ .reg .u64 t; cvta.to.shared.u64 t, %1; cvt.u32.u64 %0, t; }" : "=r"(a) : "l"(p));
    return a;
}
__device__ __forceinline__ void cp16(uint32_t dst, const void* src, int nbytes) {
    asm volatile("cp.async.cg.shared.global [%0], [%1], 16, %2;"
                 :: "r"(dst), "l"(src), "r"(nbytes));
}
__device__ __forceinline__ float roundtf(float f) {
    uint32_t r;
    asm("cvt.rna.tf32.f32 %0, %1;" : "=r"(r) : "f"(f));
    return __uint_as_float(r);
}
__device__ __forceinline__ void mma_tf32(float* c, const uint32_t* a, const uint32_t* b) {
    asm volatile(
        "mma.sync.aligned.m16n8k8.row.col.f32.tf32.tf32.f32 "
        "{%0,%1,%2,%3}, {%4,%5,%6,%7}, {%8,%9}, {%0,%1,%2,%3};"
        : "+f"(c[0]), "+f"(c[1]), "+f"(c[2]), "+f"(c[3])
        : "r"(a[0]), "r"(a[1]), "r"(a[2]), "r"(a[3]), "r"(b[0]), "r"(b[1]));
}

// ---------------- tf32 mma.sync NT GEMM (3-stage cp.async pipeline) ----------
// C[M,Nv] = alpha * A[M,K] * B[Nv,K]^T
// batch z: zh = z>>zShift, zl = z & mask; per-operand offset zh*Hi + zl*Lo.
// roundB: RNA-round the B tile in smem before use (B may be raw fp32).
struct GArgs {
    const float* A; const float* B; float* C;
    int M, Nv, K;
    int lda, ldb; long ldc;
    int zShift;
    long aHi, aLo, bHi, bLo, cHi, cLo;
    int roundC; int roundB;
    float alpha;
};

constexpr int TM_ = 128, TN_ = 128, TK_ = 32;
constexpr int STAGE_F    = TM_ * TK_ + TN_ * TK_;   // 8192 floats
constexpr int NSTAGE     = 3;
constexpr int SMEM_BYTES = NSTAGE * STAGE_F * 4;    // 98304

__device__ __forceinline__ int sw_idx(int r, int c) {
    return r * 32 + ((((c >> 2) ^ (r & 7)) << 2) | (c & 3));
}

__global__ void __launch_bounds__(256, 2) gemm_tc(GArgs g)
{
    extern __shared__ __align__(128) float smem[];
    const uint32_t sbase = smem_u32(smem);
    const int tid  = threadIdx.x;
    const int wid  = tid >> 5, lane = tid & 31;
    const int grp  = lane >> 2, tg = lane & 3;

    const int z  = blockIdx.z;
    const long zh = z >> g.zShift;
    const long zl = z & ((1 << g.zShift) - 1);
    const float* A = g.A + zh * g.aHi + zl * g.aLo;
    const float* B = g.B + zh * g.bHi + zl * g.bLo;
    float* C = g.C + zh * g.cHi + zl * g.cLo;

    const int m0 = blockIdx.y * TM_, n0 = blockIdx.x * TN_;
    const int M = g.M, Nv = g.Nv, K = g.K;
    const long lda = g.lda, ldb = g.ldb;
    const int nchunks = (K + TK_ - 1) / TK_;

    const int wrow0 = (wid & 1) * 64;
    const int wcol0 = (wid >> 1) * 32;

    float acc[4][4][4] = {};

    auto load_chunk = [&](int buf, int c) {
        const long k0 = (long)c * TK_;
        const uint32_t sA = sbase + buf * (STAGE_F * 4);
        const uint32_t sB = sA + TM_ * TK_ * 4;
#pragma unroll
        for (int i = 0; i < 4; ++i) {
            int l = tid + i * 256, r = l >> 3, seg = l & 7;
            long grow = m0 + r, gk = k0 + seg * 4;
            bool ok = (grow < M) && (gk < K);
            const float* src = ok ? (A + grow * lda + gk) : A;
            uint32_t off = (uint32_t)(r * 128 + (seg ^ (r & 7)) * 16);
            cp16(sA + off, src, ok ? 16 : 0);
        }
#pragma unroll
        for (int i = 0; i < 4; ++i) {
            int l = tid + i * 256, r = l >> 3, seg = l & 7;
            long grow = n0 + r, gk = k0 + seg * 4;
            bool ok = (grow < Nv) && (gk < K);
            const float* src = ok ? (B + grow * ldb + gk) : B;
            uint32_t off = (uint32_t)(r * 128 + (seg ^ (r & 7)) * 16);
            cp16(sB + off, src, ok ? 16 : 0);
        }
        asm volatile("cp.async.commit_group;");
    };

    load_chunk(0, 0);
    if (nchunks > 1) load_chunk(1, 1);

    int buf = 0;
    for (int c = 0; c < nchunks; ++c) {
        if (c + 2 < nchunks) {
            int nb = buf + 2; if (nb >= NSTAGE) nb -= NSTAGE;
            load_chunk(nb, c + 2);
            asm volatile("cp.async.wait_group 2;");
        } else if (c + 1 < nchunks) {
            asm volatile("cp.async.wait_group 1;");
        } else {
            asm volatile("cp.async.wait_group 0;");
        }
        __syncthreads();

        if (g.roundB) {
            float4* bp = (float4*)(smem + buf * STAGE_F + TM_ * TK_);
#pragma unroll
            for (int q = 0; q < 4; ++q) {
                float4 v = bp[tid + q * 256];
                v.x = roundtf(v.x); v.y = roundtf(v.y);
                v.z = roundtf(v.z); v.w = roundtf(v.w);
                bp[tid + q * 256] = v;
            }
            __syncthreads();
        }

        const float* As = smem + buf * STAGE_F;
        const float* Bs = As + TM_ * TK_;
        // k-permutation (HW col t <- logical 2t, t+4 <- 2t+1) on both operands:
        // dot-product invariant; fragment pairs become one 8-byte LDS.
#pragma unroll
        for (int ks = 0; ks < 4; ++ks) {
            const int cA = ks * 8 + 2 * tg;
            uint32_t af[4][4], bf[4][2];
#pragma unroll
            for (int mt = 0; mt < 4; ++mt) {
                int r0 = wrow0 + mt * 16 + grp;
                uint2 lo = *(const uint2*)&As[sw_idx(r0,     cA)];
                uint2 hi = *(const uint2*)&As[sw_idx(r0 + 8, cA)];
                af[mt][0] = lo.x; af[mt][1] = hi.x; af[mt][2] = lo.y; af[mt][3] = hi.y;
            }
#pragma unroll
            for (int nt = 0; nt < 4; ++nt) {
                int rn = wcol0 + nt * 8 + grp;
                uint2 bb = *(const uint2*)&Bs[sw_idx(rn, cA)];
                bf[nt][0] = bb.x; bf[nt][1] = bb.y;
            }
#pragma unroll
            for (int mt = 0; mt < 4; ++mt)
#pragma unroll
                for (int nt = 0; nt < 4; ++nt)
                    mma_tf32(acc[mt][nt], af[mt], bf[nt]);
        }
        __syncthreads();
        if (++buf == NSTAGE) buf = 0;
    }

    const float alpha = g.alpha;
    const int rC = g.roundC;
#pragma unroll
    for (int mt = 0; mt < 4; ++mt) {
#pragma unroll
        for (int nt = 0; nt < 4; ++nt) {
            long r0 = m0 + wrow0 + mt * 16 + grp;
            long cc = n0 + wcol0 + nt * 8 + tg * 2;
            if (cc < Nv) {
#pragma unroll
                for (int h = 0; h < 2; ++h) {
                    long rr = r0 + 8 * h;
                    if (rr < M) {
                        float v0 = alpha * acc[mt][nt][2 * h];
                        float v1 = alpha * acc[mt][nt][2 * h + 1];
                        if (rC) { v0 = roundtf(v0); v1 = roundtf(v1); }
                        C[rr * g.ldc + cc]     = v0;
                        C[rr * g.ldc + cc + 1] = v1;
                    }
                }
            }
        }
    }
}

// ---------------- vectorized 64x64 transpose+round ---------------------------
// prep_s: g_St[b][e][tm] = round(s_b[tm][e]);  dims tm=8576, e=1024 (both /64)
__global__ void prep_s(const float* __restrict__ s1, const float* __restrict__ s2,
                       const float* __restrict__ s3, const float* __restrict__ s4)
{
    __shared__ float t[64][68];        // [e_local][tm_local], pad for 16B LDS
    const int b = blockIdx.z;
    const float* src = (b == 0) ? s1 : (b == 1) ? s2 : (b == 2) ? s3 : s4;
    float* dst = g_St + (size_t)b * SNE;
    const int e0  = blockIdx.x * 64;
    const int tm0 = blockIdx.y * 64;
    const int tid = threadIdx.x;
    const int jr = tid & 15, ir = tid >> 4;
#pragma unroll
    for (int p = 0; p < 4; ++p) {
        int r = ir + p * 16;
        float4 v = *(const float4*)&src[(size_t)(tm0 + r) * cE + e0 + 4 * jr];
        t[4 * jr + 0][r] = roundtf(v.x);
        t[4 * jr + 1][r] = roundtf(v.y);
        t[4 * jr + 2][r] = roundtf(v.z);
        t[4 * jr + 3][r] = roundtf(v.w);
    }
    __syncthreads();
#pragma unroll
    for (int p = 0; p < 4; ++p) {
        int e = ir + p * 16;
        float4 v;
        v.x = t[e][4 * jr + 0]; v.y = t[e][4 * jr + 1];
        v.z = t[e][4 * jr + 2]; v.w = t[e][4 * jr + 3];
        *(float4*)&dst[(size_t)(e0 + e) * TNK + tm0 + 4 * jr] = v;
    }
}

// transpose+round 1024x1024 weights: g_WvT[z][f][e] = round(src_z[e][f])
__global__ void transpose_wv(const float* __restrict__ wv_b, const float* __restrict__ wv)
{
    __shared__ float t[64][68];
    const int z = blockIdx.z;
    const float* src = (z < 4) ? wv_b + (size_t)z * MM : wv;
    float* dst = g_WvT + (size_t)z * MM;
    const int f0 = blockIdx.x * 64;    // dst row dim
    const int e0 = blockIdx.y * 64;    // src row dim
    const int tid = threadIdx.x;
    const int jr = tid & 15, ir = tid >> 4;
#pragma unroll
    for (int p = 0; p < 4; ++p) {
        int r = ir + p * 16;
        float4 v = *(const float4*)&src[(size_t)(e0 + r) * 1024 + f0 + 4 * jr];
        t[4 * jr + 0][r] = roundtf(v.x);
        t[4 * jr + 1][r] = roundtf(v.y);
        t[4 * jr + 2][r] = roundtf(v.z);
        t[4 * jr + 3][r] = roundtf(v.w);
    }
    __syncthreads();
#pragma unroll
    for (int p = 0; p < 4; ++p) {
        int f = ir + p * 16;
        float4 v;
        v.x = t[f][4 * jr + 0]; v.y = t[f][4 * jr + 1];
        v.z = t[f][4 * jr + 2]; v.w = t[f][4 * jr + 3];
        *(float4*)&dst[(size_t)(f0 + f) * 1024 + e0 + 4 * jr] = v;
    }
}

// ---------------- rounding copies --------------------------------------------
__global__ void convert_F(const float* __restrict__ f)
{
    long i = blockIdx.x * (long)blockDim.x + threadIdx.x;
    if (i < (long)(cN * cE) / 4) {
        float4 v = ((const float4*)f)[i];
        v.x = roundtf(v.x); v.y = roundtf(v.y);
        v.z = roundtf(v.z); v.w = roundtf(v.w);
        ((float4*)g_F)[i] = v;
    }
}

__global__ void round_weights(const float* __restrict__ wq_b, const float* __restrict__ wk_b,
                              const float* __restrict__ wq,   const float* __restrict__ wk)
{
    const int z = blockIdx.z;
    const float* src = (z < 4) ? wq_b + (size_t)z * MM
                     : (z == 4) ? wq
                     : (z < 9) ? wk_b + (size_t)(z - 5) * MM
                     : wk;
    const float4* s4 = (const float4*)src;
    float4* d4 = (float4*)(g_Wr + (size_t)z * MM);
    const long n4 = (long)MM / 4;
    for (long i = blockIdx.x * (long)blockDim.x + threadIdx.x; i < n4;
         i += (long)gridDim.x * blockDim.x) {
        float4 v = s4[i];
        v.x = roundtf(v.x); v.y = roundtf(v.y);
        v.z = roundtf(v.z); v.w = roundtf(v.w);
        d4[i] = v;
    }
}

// generic scalar transpose+round: dst[c*R + r] = round(src[r*Cc + c])
__global__ void transpose_g(const float* __restrict__ src, float* __restrict__ dst,
                            int R, int Cc)
{
    __shared__ float t[32][33];
    const int x0 = blockIdx.x * 32, y0 = blockIdx.y * 32;
#pragma unroll
    for (int i = threadIdx.y; i < 32; i += 8) {
        int y = y0 + i, x = x0 + threadIdx.x;
        t[i][threadIdx.x] = (y < R && x < Cc) ? src[(size_t)y * Cc + x] : 0.f;
    }
    __syncthreads();
#pragma unroll
    for (int i = threadIdx.y; i < 32; i += 8) {
        int x = x0 + i, y = y0 + threadIdx.x;
        if (x < Cc && y < R) dst[(size_t)x * R + y] = roundtf(t[threadIdx.x][i]);
    }
}

// U[b] = round(sum of 4 split-K partials) -- stage1 layout [b][ks][NE]
__global__ void reduce4()
{
    const int b = blockIdx.z;
    const float4* p0 = (const float4*)(g_UP + (size_t)(b * 4 + 0) * NE);
    const float4* p1 = (const float4*)(g_UP + (size_t)(b * 4 + 1) * NE);
    const float4* p2 = (const float4*)(g_UP + (size_t)(b * 4 + 2) * NE);
    const float4* p3 = (const float4*)(g_UP + (size_t)(b * 4 + 3) * NE);
    float4* d = (float4*)(g_U + (size_t)b * NE);
    long i = blockIdx.x * (long)blockDim.x + threadIdx.x;
    if (i < (long)NE / 4) {
        float4 a = p0[i], x = p1[i], y = p2[i], w = p3[i];
        float4 r;
        r.x = roundtf(a.x + x.x + y.x + w.x);
        r.y = roundtf(a.y + x.y + y.y + w.y);
        r.z = roundtf(a.z + x.z + y.z + w.z);
        r.w = roundtf(a.w + x.w + y.w + w.w);
        d[i] = r;
    }
}

// dst[i] = (round?) sum of 4 parts at stride part4 (float4 units)
__global__ void reduce_k(const float4* __restrict__ src, float4* __restrict__ dst,
                         long part4, long n4, int doRound)
{
    long i = blockIdx.x * (long)blockDim.x + threadIdx.x;
    if (i < n4) {
        float4 a = src[i], b = src[i + part4], c = src[i + 2 * part4], d = src[i + 3 * part4];
        float4 r;
        r.x = a.x + b.x + c.x + d.x;
        r.y = a.y + b.y + c.y + d.y;
        r.z = a.z + b.z + c.z + d.z;
        r.w = a.w + b.w + c.w + d.w;
        if (doRound) { r.x = roundtf(r.x); r.y = roundtf(r.y); r.z = roundtf(r.z); r.w = roundtf(r.w); }
        dst[i] = r;
    }
}

// ---------------- softmax (warp per row of 268; rounds output) ---------------
__global__ __launch_bounds__(256) void softmax_kernel(float* __restrict__ base, int rows)
{
    int w = (blockIdx.x * blockDim.x + threadIdx.x) >> 5;
    int lane = threadIdx.x & 31;
    if (w >= rows) return;
    float* row = base + (size_t)w * cN;

    float v[9];
    float m = -1e30f;
#pragma unroll
    for (int j = 0; j < 9; ++j) {
        int c = lane + 32 * j;
        v[j] = (c < cN) ? row[c] : -1e30f;
        m = fmaxf(m, v[j]);
    }
#pragma unroll
    for (int o = 16; o; o >>= 1) m = fmaxf(m, __shfl_xor_sync(0xffffffffu, m, o));
    float s = 0.f;
#pragma unroll
    for (int j = 0; j < 9; ++j) { v[j] = expf(v[j] - m); s += v[j]; }
#pragma unroll
    for (int o = 16; o; o >>= 1) s += __shfl_xor_sync(0xffffffffu, s, o);
    float inv = 1.f / s;
#pragma unroll
    for (int j = 0; j < 9; ++j) {
        int c = lane + 32 * j;
        if (c < cN) row[c] = roundtf(v[j] * inv);
    }
}

// ---------------- launch -----------------------------------------------------
static inline void launch_gemm(const GArgs& a, int batch)
{
    dim3 grid((a.Nv + TN_ - 1) / TN_, (a.M + TM_ - 1) / TM_, batch);
    gemm_tc<<<grid, 256, SMEM_BYTES>>>(a);
}

extern "C" void kernel_launch(void* const* d_in, const int* in_sizes, int n_in,
                              void* d_out, int out_size)
{
    const float* features = (const float*)d_in[0];
    const float* s1 = (const float*)d_in[1];
    const float* s2 = (const float*)d_in[2];
    const float* s3 = (const float*)d_in[3];
    const float* s4 = (const float*)d_in[4];
    const float* wq_b = (const float*)d_in[5];
    const float* wk_b = (const float*)d_in[6];
    const float* wv_b = (const float*)d_in[7];
    const float* wq   = (const float*)d_in[8];
    const float* wk   = (const float*)d_in[9];
    const float* wv   = (const float*)d_in[10];
    float* out = (float*)d_out;

    cudaFuncSetAttribute(gemm_tc, cudaFuncAttributeMaxDynamicSharedMemorySize, SMEM_BYTES);

    float *Wr, *WvT, *G, *F, *St, *QH, *P, *UP, *U, *MSp, *MST, *P2, *U2;
    cudaGetSymbolAddress((void**)&Wr,  g_Wr);
    cudaGetSymbolAddress((void**)&WvT, g_WvT);
    cudaGetSymbolAddress((void**)&G,   g_G);
    cudaGetSymbolAddress((void**)&F,   g_F);
    cudaGetSymbolAddress((void**)&St,  g_St);
    cudaGetSymbolAddress((void**)&QH,  g_qh);
    cudaGetSymbolAddress((void**)&P,   g_P);
    cudaGetSymbolAddress((void**)&UP,  g_UP);
    cudaGetSymbolAddress((void**)&U,   g_U);
    cudaGetSymbolAddress((void**)&MSp, g_ms);
    cudaGetSymbolAddress((void**)&MST, g_MST);
    cudaGetSymbolAddress((void**)&P2,  g_P2);
    cudaGetSymbolAddress((void**)&U2,  g_U2);

    const float* s_in[4] = { s1, s2, s3, s4 };

    // 0) prep: round F; transpose+round s -> St; round wq/wk; wv^T
    convert_F<<<(cN * cE / 4 + 255) / 256, 256>>>(features);
    prep_s<<<dim3(cE / 64, TNK / 64, 4), 256>>>(s1, s2, s3, s4);
    round_weights<<<dim3(256, 1, 10), 256>>>(wq_b, wk_b, wq, wk);
    transpose_wv<<<dim3(16, 16, 5), 256>>>(wv_b, wv);

    // 1) fold Gt[z] = wk_z * wq_z^T  (z=0..3 branches, z=4 stage2)
    launch_gemm({Wr + 5 * MM, Wr, G, 1024, 1024, 1024, 1024, 1024, 1024,
                 0, (long)MM, 0, (long)MM, 0, (long)MM, 0, 1, 0, 1.f}, 5);

    // 2) q~[z] = F @ Gt[z]^T  [268x1024]
    launch_gemm({F, G, QH, cN, 1024, 1024, 1024, 1024, 1024,
                 0, 0, 0, (long)MM, 0, (long)NE, 0, 1, 0, 1.f}, 5);

    // 3) stage-1 scores: P[b] = scale * q~_b @ s_b^T  (raw s, rounded in smem)
    for (int b = 0; b < 4; ++b)
        launch_gemm({QH + (size_t)b * NE, s_in[b], P + (size_t)b * cN * TNK,
                     cN, TNK, 1024, 1024, cE, (long)TNK,
                     0, 0, 0, 0, 0, 0, 0, 0, 1, cScale}, 1);

    // 4) softmax over 34304 segments of 268
    {
        int rows = cB * cN * cS;
        softmax_kernel<<<(rows + 7) / 8, 256>>>(P, rows);
    }

    // 5) U partials (z = b*4+ks) then reduce
    launch_gemm({P, St, UP, cN, 1024, KCH, TNK, TNK, 1024,
                 2, (long)cN * TNK, (long)KCH, (long)SNE, (long)KCH,
                 (long)(4 * NE), (long)NE, 0, 0, 1.f}, 16);
    reduce4<<<dim3((int)(NE / 4 / 256), 1, 4), 256>>>();

    // 6) ms_b = U_b @ wv_b
    launch_gemm({U, WvT, MSp, cN, 1024, 1024, 1024, 1024, 1024,
                 0, (long)NE, 0, (long)MM, 0, (long)NE, 0, 1, 0, 1.f}, 4);

    // 7) stage-2 scores split-K x4 -> partials -> P2
    {
        const long p4 = (long)(cN * 4 * cN) / 4;     // 71824
        launch_gemm({QH + 4 * NE, MSp, UP, cN, 4 * cN, 256, 1024, 1024, (long)(4 * cN),
                     0, 256, 0, 256, 0, (long)(cN * 4 * cN), 0, 0, 0, cScale}, 4);
        reduce_k<<<(int)((p4 + 255) / 256), 256>>>((const float4*)UP, (float4*)P2, p4, p4, 0);
    }
    softmax_kernel<<<(4 * cN + 7) / 8, 256>>>(P2, 4 * cN);

    // 8) U2 = P2 @ ms (split-K x4 over 1072; needs ms^T)
    transpose_g<<<dim3(32, (4 * cN + 31) / 32, 1), dim3(32, 8)>>>(MSp, MST, 4 * cN, 1024);
    {
        const long p4 = (long)NE / 4;
        launch_gemm({P2, MST, UP, cN, 1024, 268, 4 * cN, 4 * cN, 1024,
                     0, 268, 0, 268, 0, (long)NE, 0, 0, 0, 1.f}, 4);
        reduce_k<<<(int)((p4 + 255) / 256), 256>>>((const float4*)UP, (float4*)U2, p4, p4, 1);
    }

    // 9) out = U2 @ wv (split-K x4)
    {
        const long p4 = (long)NE / 4;
        launch_gemm({U2, WvT + 4 * MM, UP, cN, 1024, 256, 1024, 1024, 1024,
                     0, 256, 0, 256, 0, (long)NE, 0, 0, 0, 1.f}, 4);
        reduce_k<<<(int)((p4 + 255) / 256), 256>>>((const float4*)UP, (float4*)out, p4, p4, 0);
    }
}

// round 10
// speedup vs baseline: 1.0847x; 1.0847x over previous
#include <cuda_runtime.h>
#include <stdint.h>

// ---------------- problem constants ----------------------------------------
constexpr int cN = 268, cS = 32, cE = 1024, cB = 4;
constexpr float cScale = 0.03125f;           // 1/sqrt(1024)
constexpr size_t MM  = 1024ull * 1024ull;
constexpr int   TNK  = cS * cN;              // 8576
constexpr size_t NE  = (size_t)cN * cE;      // 274432
constexpr size_t SNE = (size_t)TNK * cE;     // 8781824
constexpr int   KCH  = TNK / 4;              // 2144

// ---------------- scratch (device globals) ----------------------------------
__device__ __align__(1024) float g_WvT[5 * MM];    // transposed+rounded: wv_b(0-3), wv(4)
__device__ __align__(1024) float g_G  [5 * MM];    // Gt = wk*wq^T per branch + stage2
__device__ __align__(1024) float g_St [4 * SNE];   // rounded transposed snapshots [b][e][tm]
__device__ __align__(1024) float g_qh [5 * NE];    // q-tilde per branch + stage2
__device__ __align__(1024) float g_P  [(size_t)cB * cN * TNK];  // probs [b][n][t*m]
__device__ __align__(1024) float g_UP [16 * NE];   // partials scratch (reused)
__device__ __align__(1024) float g_U  [4 * NE];    // U reduced+rounded
__device__ __align__(1024) float g_ms [4 * NE];    // branch outputs (rounded)
__device__ __align__(1024) float g_MST[(size_t)cE * 4 * cN];    // ms^T [e][tm2]
__device__ __align__(1024) float g_P2 [(size_t)cN * 4 * cN];    // stage2 probs [n][t*m]
__device__ __align__(1024) float g_U2 [NE];        // stage2 U (rounded)

// ---------------- PTX helpers -----------------------------------------------
__device__ __forceinline__ uint32_t smem_u32(const void* p) {
    uint32_t a;
    asm("{ .reg .u64 t; cvta.to.shared.u64 t, %1; cvt.u32.u64 %0, t; }" : "=r"(a) : "l"(p));
    return a;
}
__device__ __forceinline__ void cp16(uint32_t dst, const void* src, int nbytes) {
    asm volatile("cp.async.cg.shared.global [%0], [%1], 16, %2;"
                 :: "r"(dst), "l"(src), "r"(nbytes));
}
__device__ __forceinline__ float roundtf(float f) {
    uint32_t r;
    asm("cvt.rna.tf32.f32 %0, %1;" : "=r"(r) : "f"(f));
    return __uint_as_float(r);
}
__device__ __forceinline__ void mma_tf32(float* c, const uint32_t* a, const uint32_t* b) {
    asm volatile(
        "mma.sync.aligned.m16n8k8.row.col.f32.tf32.tf32.f32 "
        "{%0,%1,%2,%3}, {%4,%5,%6,%7}, {%8,%9}, {%0,%1,%2,%3};"
        : "+f"(c[0]), "+f"(c[1]), "+f"(c[2]), "+f"(c[3])
        : "r"(a[0]), "r"(a[1]), "r"(a[2]), "r"(a[3]), "r"(b[0]), "r"(b[1]));
}

// ---------------- tf32 mma.sync NT GEMM (3-stage cp.async pipeline) ----------
// C[M,Nv] = alpha * A[M,K] * B[Nv,K]^T
// batch z: zh = z>>zShift, zl = z & mask; per-operand offset zh*Hi + zl*Lo.
// roundA/roundB: RNA-round the A/B tile in smem (operand may be raw fp32).
struct GArgs {
    const float* A; const float* B; float* C;
    int M, Nv, K;
    int lda, ldb; long ldc;
    int zShift;
    long aHi, aLo, bHi, bLo, cHi, cLo;
    int roundC; int roundA; int roundB;
    float alpha;
};

constexpr int TM_ = 96, TN_ = 128, TK_ = 32;
constexpr int A_F        = TM_ * TK_;               // 3072 floats
constexpr int STAGE_F    = A_F + TN_ * TK_;         // 7168 floats (28 KB)
constexpr int NSTAGE     = 3;
constexpr int SMEM_BYTES = NSTAGE * STAGE_F * 4;    // 86016

__device__ __forceinline__ int sw_idx(int r, int c) {
    return r * 32 + ((((c >> 2) ^ (r & 7)) << 2) | (c & 3));
}

__global__ void __launch_bounds__(256, 2) gemm_tc(GArgs g)
{
    extern __shared__ __align__(128) float smem[];
    const uint32_t sbase = smem_u32(smem);
    const int tid  = threadIdx.x;
    const int wid  = tid >> 5, lane = tid & 31;
    const int grp  = lane >> 2, tg = lane & 3;

    const int z  = blockIdx.z;
    const long zh = z >> g.zShift;
    const long zl = z & ((1 << g.zShift) - 1);
    const float* A = g.A + zh * g.aHi + zl * g.aLo;
    const float* B = g.B + zh * g.bHi + zl * g.bLo;
    float* C = g.C + zh * g.cHi + zl * g.cLo;

    const int m0 = blockIdx.y * TM_, n0 = blockIdx.x * TN_;
    const int M = g.M, Nv = g.Nv, K = g.K;
    const long lda = g.lda, ldb = g.ldb;
    const int nchunks = (K + TK_ - 1) / TK_;

    // warps: 2 (m) x 4 (n); warp tile 48 x 32
    const int wrow0 = (wid & 1) * 48;
    const int wcol0 = (wid >> 1) * 32;

    float acc[3][4][4] = {};

    auto load_chunk = [&](int buf, int c) {
        const long k0 = (long)c * TK_;
        const uint32_t sA = sbase + buf * (STAGE_F * 4);
        const uint32_t sB = sA + A_F * 4;
        // A: 96 rows x 8 segs(16B) = 768 segs, 3 per thread
#pragma unroll
        for (int i = 0; i < 3; ++i) {
            int l = tid + i * 256, r = l >> 3, seg = l & 7;
            long grow = m0 + r, gk = k0 + seg * 4;
            bool ok = (grow < M) && (gk < K);
            const float* src = ok ? (A + grow * lda + gk) : A;
            uint32_t off = (uint32_t)(r * 128 + (seg ^ (r & 7)) * 16);
            cp16(sA + off, src, ok ? 16 : 0);
        }
        // B: 128 rows x 8 segs = 1024 segs, 4 per thread
#pragma unroll
        for (int i = 0; i < 4; ++i) {
            int l = tid + i * 256, r = l >> 3, seg = l & 7;
            long grow = n0 + r, gk = k0 + seg * 4;
            bool ok = (grow < Nv) && (gk < K);
            const float* src = ok ? (B + grow * ldb + gk) : B;
            uint32_t off = (uint32_t)(r * 128 + (seg ^ (r & 7)) * 16);
            cp16(sB + off, src, ok ? 16 : 0);
        }
        asm volatile("cp.async.commit_group;");
    };

    load_chunk(0, 0);
    if (nchunks > 1) load_chunk(1, 1);

    int buf = 0;
    for (int c = 0; c < nchunks; ++c) {
        if (c + 2 < nchunks) {
            int nb = buf + 2; if (nb >= NSTAGE) nb -= NSTAGE;
            load_chunk(nb, c + 2);
            asm volatile("cp.async.wait_group 2;");
        } else if (c + 1 < nchunks) {
            asm volatile("cp.async.wait_group 1;");
        } else {
            asm volatile("cp.async.wait_group 0;");
        }
        __syncthreads();

        if (g.roundA || g.roundB) {
            if (g.roundA) {
                float4* ap = (float4*)(smem + buf * STAGE_F);
#pragma unroll
                for (int q = 0; q < 3; ++q) {
                    float4 v = ap[tid + q * 256];
                    v.x = roundtf(v.x); v.y = roundtf(v.y);
                    v.z = roundtf(v.z); v.w = roundtf(v.w);
                    ap[tid + q * 256] = v;
                }
            }
            if (g.roundB) {
                float4* bp = (float4*)(smem + buf * STAGE_F + A_F);
#pragma unroll
                for (int q = 0; q < 4; ++q) {
                    float4 v = bp[tid + q * 256];
                    v.x = roundtf(v.x); v.y = roundtf(v.y);
                    v.z = roundtf(v.z); v.w = roundtf(v.w);
                    bp[tid + q * 256] = v;
                }
            }
            __syncthreads();
        }

        const float* As = smem + buf * STAGE_F;
        const float* Bs = As + A_F;
        // k-permutation (HW col t <- logical 2t, t+4 <- 2t+1) on both operands:
        // dot-product invariant; fragment pairs become one 8-byte LDS.
#pragma unroll
        for (int ks = 0; ks < 4; ++ks) {
            const int cA = ks * 8 + 2 * tg;
            uint32_t af[3][4], bf[4][2];
#pragma unroll
            for (int mt = 0; mt < 3; ++mt) {
                int r0 = wrow0 + mt * 16 + grp;
                uint2 lo = *(const uint2*)&As[sw_idx(r0,     cA)];
                uint2 hi = *(const uint2*)&As[sw_idx(r0 + 8, cA)];
                af[mt][0] = lo.x; af[mt][1] = hi.x; af[mt][2] = lo.y; af[mt][3] = hi.y;
            }
#pragma unroll
            for (int nt = 0; nt < 4; ++nt) {
                int rn = wcol0 + nt * 8 + grp;
                uint2 bb = *(const uint2*)&Bs[sw_idx(rn, cA)];
                bf[nt][0] = bb.x; bf[nt][1] = bb.y;
            }
#pragma unroll
            for (int mt = 0; mt < 3; ++mt)
#pragma unroll
                for (int nt = 0; nt < 4; ++nt)
                    mma_tf32(acc[mt][nt], af[mt], bf[nt]);
        }
        __syncthreads();
        if (++buf == NSTAGE) buf = 0;
    }

    const float alpha = g.alpha;
    const int rC = g.roundC;
#pragma unroll
    for (int mt = 0; mt < 3; ++mt) {
#pragma unroll
        for (int nt = 0; nt < 4; ++nt) {
            long r0 = m0 + wrow0 + mt * 16 + grp;
            long cc = n0 + wcol0 + nt * 8 + tg * 2;
            if (cc < Nv) {
#pragma unroll
                for (int h = 0; h < 2; ++h) {
                    long rr = r0 + 8 * h;
                    if (rr < M) {
                        float v0 = alpha * acc[mt][nt][2 * h];
                        float v1 = alpha * acc[mt][nt][2 * h + 1];
                        if (rC) { v0 = roundtf(v0); v1 = roundtf(v1); }
                        C[rr * g.ldc + cc]     = v0;
                        C[rr * g.ldc + cc + 1] = v1;
                    }
                }
            }
        }
    }
}

// ---------------- vectorized 64x64 transpose+round ---------------------------
__global__ void prep_s(const float* __restrict__ s1, const float* __restrict__ s2,
                       const float* __restrict__ s3, const float* __restrict__ s4)
{
    __shared__ float t[64][68];
    const int b = blockIdx.z;
    const float* src = (b == 0) ? s1 : (b == 1) ? s2 : (b == 2) ? s3 : s4;
    float* dst = g_St + (size_t)b * SNE;
    const int e0  = blockIdx.x * 64;
    const int tm0 = blockIdx.y * 64;
    const int tid = threadIdx.x;
    const int jr = tid & 15, ir = tid >> 4;
#pragma unroll
    for (int p = 0; p < 4; ++p) {
        int r = ir + p * 16;
        float4 v = *(const float4*)&src[(size_t)(tm0 + r) * cE + e0 + 4 * jr];
        t[4 * jr + 0][r] = roundtf(v.x);
        t[4 * jr + 1][r] = roundtf(v.y);
        t[4 * jr + 2][r] = roundtf(v.z);
        t[4 * jr + 3][r] = roundtf(v.w);
    }
    __syncthreads();
#pragma unroll
    for (int p = 0; p < 4; ++p) {
        int e = ir + p * 16;
        float4 v;
        v.x = t[e][4 * jr + 0]; v.y = t[e][4 * jr + 1];
        v.z = t[e][4 * jr + 2]; v.w = t[e][4 * jr + 3];
        *(float4*)&dst[(size_t)(e0 + e) * TNK + tm0 + 4 * jr] = v;
    }
}

__global__ void transpose_wv(const float* __restrict__ wv_b, const float* __restrict__ wv)
{
    __shared__ float t[64][68];
    const int z = blockIdx.z;
    const float* src = (z < 4) ? wv_b + (size_t)z * MM : wv;
    float* dst = g_WvT + (size_t)z * MM;
    const int f0 = blockIdx.x * 64;
    const int e0 = blockIdx.y * 64;
    const int tid = threadIdx.x;
    const int jr = tid & 15, ir = tid >> 4;
#pragma unroll
    for (int p = 0; p < 4; ++p) {
        int r = ir + p * 16;
        float4 v = *(const float4*)&src[(size_t)(e0 + r) * 1024 + f0 + 4 * jr];
        t[4 * jr + 0][r] = roundtf(v.x);
        t[4 * jr + 1][r] = roundtf(v.y);
        t[4 * jr + 2][r] = roundtf(v.z);
        t[4 * jr + 3][r] = roundtf(v.w);
    }
    __syncthreads();
#pragma unroll
    for (int p = 0; p < 4; ++p) {
        int f = ir + p * 16;
        float4 v;
        v.x = t[f][4 * jr + 0]; v.y = t[f][4 * jr + 1];
        v.z = t[f][4 * jr + 2]; v.w = t[f][4 * jr + 3];
        *(float4*)&dst[(size_t)(f0 + f) * 1024 + e0 + 4 * jr] = v;
    }
}

// generic scalar transpose+round: dst[c*R + r] = round(src[r*Cc + c])
__global__ void transpose_g(const float* __restrict__ src, float* __restrict__ dst,
                            int R, int Cc)
{
    __shared__ float t[32][33];
    const int x0 = blockIdx.x * 32, y0 = blockIdx.y * 32;
#pragma unroll
    for (int i = threadIdx.y; i < 32; i += 8) {
        int y = y0 + i, x = x0 + threadIdx.x;
        t[i][threadIdx.x] = (y < R && x < Cc) ? src[(size_t)y * Cc + x] : 0.f;
    }
    __syncthreads();
#pragma unroll
    for (int i = threadIdx.y; i < 32; i += 8) {
        int x = x0 + i, y = y0 + threadIdx.x;
        if (x < Cc && y < R) dst[(size_t)x * R + y] = roundtf(t[threadIdx.x][i]);
    }
}

// U[b] = round(sum of 4 split-K partials)
__global__ void reduce4()
{
    const int b = blockIdx.z;
    const float4* p0 = (const float4*)(g_UP + (size_t)(b * 4 + 0) * NE);
    const float4* p1 = (const float4*)(g_UP + (size_t)(b * 4 + 1) * NE);
    const float4* p2 = (const float4*)(g_UP + (size_t)(b * 4 + 2) * NE);
    const float4* p3 = (const float4*)(g_UP + (size_t)(b * 4 + 3) * NE);
    float4* d = (float4*)(g_U + (size_t)b * NE);
    long i = blockIdx.x * (long)blockDim.x + threadIdx.x;
    if (i < (long)NE / 4) {
        float4 a = p0[i], x = p1[i], y = p2[i], w = p3[i];
        float4 r;
        r.x = roundtf(a.x + x.x + y.x + w.x);
        r.y = roundtf(a.y + x.y + y.y + w.y);
        r.z = roundtf(a.z + x.z + y.z + w.z);
        r.w = roundtf(a.w + x.w + y.w + w.w);
        d[i] = r;
    }
}

// dst[i] = (round?) sum of 4 parts at stride part4 (float4 units)
__global__ void reduce_k(const float4* __restrict__ src, float4* __restrict__ dst,
                         long part4, long n4, int doRound)
{
    long i = blockIdx.x * (long)blockDim.x + threadIdx.x;
    if (i < n4) {
        float4 a = src[i], b = src[i + part4], c = src[i + 2 * part4], d = src[i + 3 * part4];
        float4 r;
        r.x = a.x + b.x + c.x + d.x;
        r.y = a.y + b.y + c.y + d.y;
        r.z = a.z + b.z + c.z + d.z;
        r.w = a.w + b.w + c.w + d.w;
        if (doRound) { r.x = roundtf(r.x); r.y = roundtf(r.y); r.z = roundtf(r.z); r.w = roundtf(r.w); }
        dst[i] = r;
    }
}

// ---------------- softmax (warp per row of 268; rounds output) ---------------
__global__ __launch_bounds__(256) void softmax_kernel(float* __restrict__ base, int rows)
{
    int w = (blockIdx.x * blockDim.x + threadIdx.x) >> 5;
    int lane = threadIdx.x & 31;
    if (w >= rows) return;
    float* row = base + (size_t)w * cN;

    float v[9];
    float m = -1e30f;
#pragma unroll
    for (int j = 0; j < 9; ++j) {
        int c = lane + 32 * j;
        v[j] = (c < cN) ? row[c] : -1e30f;
        m = fmaxf(m, v[j]);
    }
#pragma unroll
    for (int o = 16; o; o >>= 1) m = fmaxf(m, __shfl_xor_sync(0xffffffffu, m, o));
    float s = 0.f;
#pragma unroll
    for (int j = 0; j < 9; ++j) { v[j] = expf(v[j] - m); s += v[j]; }
#pragma unroll
    for (int o = 16; o; o >>= 1) s += __shfl_xor_sync(0xffffffffu, s, o);
    float inv = 1.f / s;
#pragma unroll
    for (int j = 0; j < 9; ++j) {
        int c = lane + 32 * j;
        if (c < cN) row[c] = roundtf(v[j] * inv);
    }
}

// ---------------- launch -----------------------------------------------------
static inline void launch_gemm(const GArgs& a, int batch)
{
    dim3 grid((a.Nv + TN_ - 1) / TN_, (a.M + TM_ - 1) / TM_, batch);
    gemm_tc<<<grid, 256, SMEM_BYTES>>>(a);
}

extern "C" void kernel_launch(void* const* d_in, const int* in_sizes, int n_in,
                              void* d_out, int out_size)
{
    const float* features = (const float*)d_in[0];
    const float* s1 = (const float*)d_in[1];
    const float* s2 = (const float*)d_in[2];
    const float* s3 = (const float*)d_in[3];
    const float* s4 = (const float*)d_in[4];
    const float* wq_b = (const float*)d_in[5];
    const float* wk_b = (const float*)d_in[6];
    const float* wv_b = (const float*)d_in[7];
    const float* wq   = (const float*)d_in[8];
    const float* wk   = (const float*)d_in[9];
    const float* wv   = (const float*)d_in[10];
    float* out = (float*)d_out;

    cudaFuncSetAttribute(gemm_tc, cudaFuncAttributeMaxDynamicSharedMemorySize, SMEM_BYTES);

    float *WvT, *G, *St, *QH, *P, *UP, *U, *MSp, *MST, *P2, *U2;
    cudaGetSymbolAddress((void**)&WvT, g_WvT);
    cudaGetSymbolAddress((void**)&G,   g_G);
    cudaGetSymbolAddress((void**)&St,  g_St);
    cudaGetSymbolAddress((void**)&QH,  g_qh);
    cudaGetSymbolAddress((void**)&P,   g_P);
    cudaGetSymbolAddress((void**)&UP,  g_UP);
    cudaGetSymbolAddress((void**)&U,   g_U);
    cudaGetSymbolAddress((void**)&MSp, g_ms);
    cudaGetSymbolAddress((void**)&MST, g_MST);
    cudaGetSymbolAddress((void**)&P2,  g_P2);
    cudaGetSymbolAddress((void**)&U2,  g_U2);

    const float* s_in[4] = { s1, s2, s3, s4 };

    // 0) prep: transpose+round s -> St; wv^T (rounded)
    prep_s<<<dim3(cE / 64, TNK / 64, 4), 256>>>(s1, s2, s3, s4);
    transpose_wv<<<dim3(16, 16, 5), 256>>>(wv_b, wv);

    // 1) fold Gt[z] = wk_z * wq_z^T  (raw weights, rounded in smem)
    //    z=0..3: wk_b[z], wq_b[z]; z=4: wk, wq  -- batched via two launches
    launch_gemm({wk_b, wq_b, G, 1024, 1024, 1024, 1024, 1024, 1024,
                 0, (long)MM, 0, (long)MM, 0, (long)MM, 0, 1, 1, 1, 1.f}, 4);
    launch_gemm({wk, wq, G + 4 * MM, 1024, 1024, 1024, 1024, 1024, 1024,
                 0, 0, 0, 0, 0, 0, 0, 1, 1, 1, 1.f}, 1);

    // 2) q~[z] = features @ Gt[z]^T  (raw F rounded in smem)  [268x1024]
    launch_gemm({features, G, QH, cN, 1024, 1024, 1024, 1024, 1024,
                 0, 0, 0, (long)MM, 0, (long)NE, 0, 1, 1, 0, 1.f}, 5);

    // 3) stage-1 scores: P[b] = scale * q~_b @ s_b^T  (raw s rounded in smem)
    for (int b = 0; b < 4; ++b)
        launch_gemm({QH + (size_t)b * NE, s_in[b], P + (size_t)b * cN * TNK,
                     cN, TNK, 1024, 1024, cE, (long)TNK,
                     0, 0, 0, 0, 0, 0, 0, 0, 0, 1, cScale}, 1);

    // 4) softmax over 34304 segments of 268
    {
        int rows = cB * cN * cS;
        softmax_kernel<<<(rows + 7) / 8, 256>>>(P, rows);
    }

    // 5) U partials (z = b*4+ks) then reduce
    launch_gemm({P, St, UP, cN, 1024, KCH, TNK, TNK, 1024,
                 2, (long)cN * TNK, (long)KCH, (long)SNE, (long)KCH,
                 (long)(4 * NE), (long)NE, 0, 0, 0, 1.f}, 16);
    reduce4<<<dim3((int)(NE / 4 / 256), 1, 4), 256>>>();

    // 6) ms_b = U_b @ wv_b
    launch_gemm({U, WvT, MSp, cN, 1024, 1024, 1024, 1024, 1024,
                 0, (long)NE, 0, (long)MM, 0, (long)NE, 0, 1, 0, 0, 1.f}, 4);

    // 7) stage-2 scores split-K x4 -> partials -> P2
    {
        const long p4 = (long)(cN * 4 * cN) / 4;
        launch_gemm({QH + 4 * NE, MSp, UP, cN, 4 * cN, 256, 1024, 1024, (long)(4 * cN),
                     0, 256, 0, 256, 0, (long)(cN * 4 * cN), 0, 0, 0, 0, cScale}, 4);
        reduce_k<<<(int)((p4 + 255) / 256), 256>>>((const float4*)UP, (float4*)P2, p4, p4, 0);
    }
    softmax_kernel<<<(4 * cN + 7) / 8, 256>>>(P2, 4 * cN);

    // 8) U2 = P2 @ ms (split-K x4 over 1072; needs ms^T)
    transpose_g<<<dim3(32, (4 * cN + 31) / 32, 1), dim3(32, 8)>>>(MSp, MST, 4 * cN, 1024);
    {
        const long p4 = (long)NE / 4;
        launch_gemm({P2, MST, UP, cN, 1024, 268, 4 * cN, 4 * cN, 1024,
                     0, 268, 0, 268, 0, (long)NE, 0, 0, 0, 0, 1.f}, 4);
        reduce_k<<<(int)((p4 + 255) / 256), 256>>>((const float4*)UP, (float4*)U2, p4, p4, 1);
    }

    // 9) out = U2 @ wv (split-K x4)
    {
        const long p4 = (long)NE / 4;
        launch_gemm({U2, WvT + 4 * MM, UP, cN, 1024, 256, 1024, 1024, 1024,
                     0, 256, 0, 256, 0, (long)NE, 0, 0, 0, 0, 1.f}, 4);
        reduce_k<<<(int)((p4 + 255) / 256), 256>>>((const float4*)UP, (float4*)out, p4, p4, 0);
    }
}

// round 11
// speedup vs baseline: 1.2179x; 1.1229x over previous
#include <cuda_runtime.h>
#include <stdint.h>

// ---------------- problem constants ----------------------------------------
constexpr int cN = 268, cS = 32, cE = 1024, cB = 4;
constexpr float cScale = 0.03125f;           // 1/sqrt(1024)
constexpr size_t MM  = 1024ull * 1024ull;
constexpr int   TNK  = cS * cN;              // 8576
constexpr size_t NE  = (size_t)cN * cE;      // 274432
constexpr int   KCH  = TNK / 4;              // 2144

// ---------------- scratch (device globals) ----------------------------------
__device__ __align__(1024) float g_G  [5 * MM];    // Gt = wk*wq^T per branch + stage2
__device__ __align__(1024) float g_qh [5 * NE];    // q-tilde per branch + stage2
__device__ __align__(1024) float g_P  [(size_t)cB * cN * TNK];  // probs [b][n][t*m]
__device__ __align__(1024) float g_UP [16 * NE];   // partials scratch (reused)
__device__ __align__(1024) float g_U  [4 * NE];    // U reduced+rounded
__device__ __align__(1024) float g_ms [4 * NE];    // branch outputs (rounded)
__device__ __align__(1024) float g_P2 [(size_t)cN * 4 * cN];    // stage2 probs [n][t*m]
__device__ __align__(1024) float g_U2 [NE];        // stage2 U (rounded)

// ---------------- PTX helpers -----------------------------------------------
__device__ __forceinline__ uint32_t smem_u32(const void* p) {
    uint32_t a;
    asm("{ .reg .u64 t; cvta.to.shared.u64 t, %1; cvt.u32.u64 %0, t; }" : "=r"(a) : "l"(p));
    return a;
}
__device__ __forceinline__ void cp16(uint32_t dst, const void* src, int nbytes) {
    asm volatile("cp.async.cg.shared.global [%0], [%1], 16, %2;"
                 :: "r"(dst), "l"(src), "r"(nbytes));
}
__device__ __forceinline__ float roundtf(float f) {
    uint32_t r;
    asm("cvt.rna.tf32.f32 %0, %1;" : "=r"(r) : "f"(f));
    return __uint_as_float(r);
}
__device__ __forceinline__ void mma_tf32(float* c, const uint32_t* a, const uint32_t* b) {
    asm volatile(
        "mma.sync.aligned.m16n8k8.row.col.f32.tf32.tf32.f32 "
        "{%0,%1,%2,%3}, {%4,%5,%6,%7}, {%8,%9}, {%0,%1,%2,%3};"
        : "+f"(c[0]), "+f"(c[1]), "+f"(c[2]), "+f"(c[3])
        : "r"(a[0]), "r"(a[1]), "r"(a[2]), "r"(a[3]), "r"(b[0]), "r"(b[1]));
}

// ---------------- tf32 mma.sync GEMM (3-stage cp.async pipeline) -------------
// NT (bTrans=0): C = alpha * A[M,K] * B[Nv,K]^T  (B rows = Nv)
// NN (bTrans=1): C = alpha * A[M,K] * B[K,Nv]    (B rows = K; raw layout)
// Per-batch-z operand pointers come from Aarr/Barr; C = Cbase + z*cStride.
struct GArgs {
    const float* Aarr[16];
    const float* Barr[16];
    float* C;
    int M, Nv, K;
    int lda, ldb; long ldc; long cStride;
    int roundC, roundA, roundB, bTrans;
    float alpha;
};

constexpr int TM_ = 96, TN_ = 128, TK_ = 32;
constexpr int A_F        = TM_ * TK_;               // 3072 floats
constexpr int B_F        = TN_ * TK_;               // 4096 floats
constexpr int STAGE_F    = A_F + B_F;               // 7168 floats (28 KB)
constexpr int NSTAGE     = 3;
constexpr int SMEM_BYTES = NSTAGE * STAGE_F * 4;    // 86016

__device__ __forceinline__ int sw_idx(int r, int c) {
    return r * 32 + ((((c >> 2) ^ (r & 7)) << 2) | (c & 3));
}

__global__ void __launch_bounds__(256, 2) gemm_tc(GArgs g)
{
    extern __shared__ __align__(128) float smem[];
    const uint32_t sbase = smem_u32(smem);
    const int tid  = threadIdx.x;
    const int wid  = tid >> 5, lane = tid & 31;
    const int grp  = lane >> 2, tg = lane & 3;

    const int z = blockIdx.z;
    const float* A = g.Aarr[z];
    const float* B = g.Barr[z];
    float* C = g.C + (long)z * g.cStride;

    const int m0 = blockIdx.y * TM_, n0 = blockIdx.x * TN_;
    const int M = g.M, Nv = g.Nv, K = g.K;
    const long lda = g.lda, ldb = g.ldb;
    const int nchunks = (K + TK_ - 1) / TK_;
    const int bT = g.bTrans;

    const int wrow0 = (wid & 1) * 48;
    const int wcol0 = (wid >> 1) * 32;

    float acc[3][4][4] = {};

    auto load_chunk = [&](int buf, int c) {
        const long k0 = (long)c * TK_;
        const uint32_t sA = sbase + buf * (STAGE_F * 4);
        const uint32_t sB = sA + A_F * 4;
        // A: 96 rows x 8 segs(16B), 3 per thread
#pragma unroll
        for (int i = 0; i < 3; ++i) {
            int l = tid + i * 256, r = l >> 3, seg = l & 7;
            long grow = m0 + r, gk = k0 + seg * 4;
            bool ok = (grow < M) && (gk < K);
            const float* src = ok ? (A + grow * lda + gk) : A;
            uint32_t off = (uint32_t)(r * 128 + (seg ^ (r & 7)) * 16);
            cp16(sA + off, src, ok ? 16 : 0);
        }
        if (!bT) {
            // NT: B 128 rows x 8 segs
#pragma unroll
            for (int i = 0; i < 4; ++i) {
                int l = tid + i * 256, r = l >> 3, seg = l & 7;
                long grow = n0 + r, gk = k0 + seg * 4;
                bool ok = (grow < Nv) && (gk < K);
                const float* src = ok ? (B + grow * ldb + gk) : B;
                uint32_t off = (uint32_t)(r * 128 + (seg ^ (r & 7)) * 16);
                cp16(sB + off, src, ok ? 16 : 0);
            }
        } else {
            // NN: B tile = 32 k-rows x 128 n-cols; [k][n] smem, n XOR (k&6)<<2
#pragma unroll
            for (int i = 0; i < 4; ++i) {
                int l = tid + i * 256, r = l >> 5, s = l & 31;
                long gk = k0 + r, gcol = n0 + s * 4;
                bool ok = (gk < K) && (gcol < Nv);
                const float* src = ok ? (B + gk * ldb + gcol) : B;
                uint32_t off = (uint32_t)(r * 512 + (((s * 4) ^ ((r & 6) << 2)) << 2));
                cp16(sB + off, src, ok ? 16 : 0);
            }
        }
        asm volatile("cp.async.commit_group;");
    };

    load_chunk(0, 0);
    if (nchunks > 1) load_chunk(1, 1);

    int buf = 0;
    for (int c = 0; c < nchunks; ++c) {
        if (c + 2 < nchunks) {
            int nb = buf + 2; if (nb >= NSTAGE) nb -= NSTAGE;
            load_chunk(nb, c + 2);
            asm volatile("cp.async.wait_group 2;");
        } else if (c + 1 < nchunks) {
            asm volatile("cp.async.wait_group 1;");
        } else {
            asm volatile("cp.async.wait_group 0;");
        }
        __syncthreads();

        if (g.roundA || g.roundB) {
            if (g.roundA) {
                float4* ap = (float4*)(smem + buf * STAGE_F);
#pragma unroll
                for (int q = 0; q < 3; ++q) {
                    float4 v = ap[tid + q * 256];
                    v.x = roundtf(v.x); v.y = roundtf(v.y);
                    v.z = roundtf(v.z); v.w = roundtf(v.w);
                    ap[tid + q * 256] = v;
                }
            }
            if (g.roundB) {
                float4* bp = (float4*)(smem + buf * STAGE_F + A_F);
#pragma unroll
                for (int q = 0; q < 4; ++q) {
                    float4 v = bp[tid + q * 256];
                    v.x = roundtf(v.x); v.y = roundtf(v.y);
                    v.z = roundtf(v.z); v.w = roundtf(v.w);
                    bp[tid + q * 256] = v;
                }
            }
            __syncthreads();
        }

        const float* As = smem + buf * STAGE_F;
        const float* Bs = As + A_F;
        // k-permutation (HW col t <- logical 2t, t+4 <- 2t+1) on both operands.
#pragma unroll
        for (int ks = 0; ks < 4; ++ks) {
            const int cA = ks * 8 + 2 * tg;
            uint32_t af[3][4], bf[4][2];
#pragma unroll
            for (int mt = 0; mt < 3; ++mt) {
                int r0 = wrow0 + mt * 16 + grp;
                uint2 lo = *(const uint2*)&As[sw_idx(r0,     cA)];
                uint2 hi = *(const uint2*)&As[sw_idx(r0 + 8, cA)];
                af[mt][0] = lo.x; af[mt][1] = hi.x; af[mt][2] = lo.y; af[mt][3] = hi.y;
            }
            if (!bT) {
#pragma unroll
                for (int nt = 0; nt < 4; ++nt) {
                    int rn = wcol0 + nt * 8 + grp;
                    uint2 bb = *(const uint2*)&Bs[sw_idx(rn, cA)];
                    bf[nt][0] = bb.x; bf[nt][1] = bb.y;
                }
            } else {
#pragma unroll
                for (int nt = 0; nt < 4; ++nt) {
                    int rn  = wcol0 + nt * 8 + grp;
                    int nsw = rn ^ ((cA & 6) << 2);
                    bf[nt][0] = *(const uint32_t*)&Bs[cA * TN_ + nsw];
                    bf[nt][1] = *(const uint32_t*)&Bs[(cA + 1) * TN_ + nsw];
                }
            }
#pragma unroll
            for (int mt = 0; mt < 3; ++mt)
#pragma unroll
                for (int nt = 0; nt < 4; ++nt)
                    mma_tf32(acc[mt][nt], af[mt], bf[nt]);
        }
        __syncthreads();
        if (++buf == NSTAGE) buf = 0;
    }

    const float alpha = g.alpha;
    const int rC = g.roundC;
#pragma unroll
    for (int mt = 0; mt < 3; ++mt) {
#pragma unroll
        for (int nt = 0; nt < 4; ++nt) {
            long r0 = m0 + wrow0 + mt * 16 + grp;
            long cc = n0 + wcol0 + nt * 8 + tg * 2;
            if (cc < Nv) {
#pragma unroll
                for (int h = 0; h < 2; ++h) {
                    long rr = r0 + 8 * h;
                    if (rr < M) {
                        float v0 = alpha * acc[mt][nt][2 * h];
                        float v1 = alpha * acc[mt][nt][2 * h + 1];
                        if (rC) { v0 = roundtf(v0); v1 = roundtf(v1); }
                        C[rr * g.ldc + cc]     = v0;
                        C[rr * g.ldc + cc + 1] = v1;
                    }
                }
            }
        }
    }
}

// U[b] = round(sum of 4 split-K partials)
__global__ void reduce4()
{
    const int b = blockIdx.z;
    const float4* p0 = (const float4*)(g_UP + (size_t)(b * 4 + 0) * NE);
    const float4* p1 = (const float4*)(g_UP + (size_t)(b * 4 + 1) * NE);
    const float4* p2 = (const float4*)(g_UP + (size_t)(b * 4 + 2) * NE);
    const float4* p3 = (const float4*)(g_UP + (size_t)(b * 4 + 3) * NE);
    float4* d = (float4*)(g_U + (size_t)b * NE);
    long i = blockIdx.x * (long)blockDim.x + threadIdx.x;
    if (i < (long)NE / 4) {
        float4 a = p0[i], x = p1[i], y = p2[i], w = p3[i];
        float4 r;
        r.x = roundtf(a.x + x.x + y.x + w.x);
        r.y = roundtf(a.y + x.y + y.y + w.y);
        r.z = roundtf(a.z + x.z + y.z + w.z);
        r.w = roundtf(a.w + x.w + y.w + w.w);
        d[i] = r;
    }
}

// dst[i] = (round?) sum of 4 parts at stride part4 (float4 units)
__global__ void reduce_k(const float4* __restrict__ src, float4* __restrict__ dst,
                         long part4, long n4, int doRound)
{
    long i = blockIdx.x * (long)blockDim.x + threadIdx.x;
    if (i < n4) {
        float4 a = src[i], b = src[i + part4], c = src[i + 2 * part4], d = src[i + 3 * part4];
        float4 r;
        r.x = a.x + b.x + c.x + d.x;
        r.y = a.y + b.y + c.y + d.y;
        r.z = a.z + b.z + c.z + d.z;
        r.w = a.w + b.w + c.w + d.w;
        if (doRound) { r.x = roundtf(r.x); r.y = roundtf(r.y); r.z = roundtf(r.z); r.w = roundtf(r.w); }
        dst[i] = r;
    }
}

// ---------------- softmax (warp per row of 268; rounds output) ---------------
__global__ __launch_bounds__(256) void softmax_kernel(float* __restrict__ base, int rows)
{
    int w = (blockIdx.x * blockDim.x + threadIdx.x) >> 5;
    int lane = threadIdx.x & 31;
    if (w >= rows) return;
    float* row = base + (size_t)w * cN;

    float v[9];
    float m = -1e30f;
#pragma unroll
    for (int j = 0; j < 9; ++j) {
        int c = lane + 32 * j;
        v[j] = (c < cN) ? row[c] : -1e30f;
        m = fmaxf(m, v[j]);
    }
#pragma unroll
    for (int o = 16; o; o >>= 1) m = fmaxf(m, __shfl_xor_sync(0xffffffffu, m, o));
    float s = 0.f;
#pragma unroll
    for (int j = 0; j < 9; ++j) { v[j] = expf(v[j] - m); s += v[j]; }
#pragma unroll
    for (int o = 16; o; o >>= 1) s += __shfl_xor_sync(0xffffffffu, s, o);
    float inv = 1.f / s;
#pragma unroll
    for (int j = 0; j < 9; ++j) {
        int c = lane + 32 * j;
        if (c < cN) row[c] = roundtf(v[j] * inv);
    }
}

// ---------------- launch -----------------------------------------------------
static inline void launch_gemm(const GArgs& a, int batch)
{
    dim3 grid((a.Nv + TN_ - 1) / TN_, (a.M + TM_ - 1) / TM_, batch);
    gemm_tc<<<grid, 256, SMEM_BYTES>>>(a);
}

extern "C" void kernel_launch(void* const* d_in, const int* in_sizes, int n_in,
                              void* d_out, int out_size)
{
    const float* features = (const float*)d_in[0];
    const float* s_in[4]  = { (const float*)d_in[1], (const float*)d_in[2],
                              (const float*)d_in[3], (const float*)d_in[4] };
    const float* wq_b = (const float*)d_in[5];
    const float* wk_b = (const float*)d_in[6];
    const float* wv_b = (const float*)d_in[7];
    const float* wq   = (const float*)d_in[8];
    const float* wk   = (const float*)d_in[9];
    const float* wv   = (const float*)d_in[10];
    float* out = (float*)d_out;

    cudaFuncSetAttribute(gemm_tc, cudaFuncAttributeMaxDynamicSharedMemorySize, SMEM_BYTES);

    float *G, *QH, *P, *UP, *U, *MSp, *P2, *U2;
    cudaGetSymbolAddress((void**)&G,   g_G);
    cudaGetSymbolAddress((void**)&QH,  g_qh);
    cudaGetSymbolAddress((void**)&P,   g_P);
    cudaGetSymbolAddress((void**)&UP,  g_UP);
    cudaGetSymbolAddress((void**)&U,   g_U);
    cudaGetSymbolAddress((void**)&MSp, g_ms);
    cudaGetSymbolAddress((void**)&P2,  g_P2);
    cudaGetSymbolAddress((void**)&U2,  g_U2);

    // 1) fold Gt[z] = wk_z * wq_z^T  (raw, NT, round in smem + on output)
    {
        GArgs a{};
        for (int z = 0; z < 4; ++z) { a.Aarr[z] = wk_b + (size_t)z * MM; a.Barr[z] = wq_b + (size_t)z * MM; }
        a.Aarr[4] = wk; a.Barr[4] = wq;
        a.C = G; a.M = 1024; a.Nv = 1024; a.K = 1024;
        a.lda = 1024; a.ldb = 1024; a.ldc = 1024; a.cStride = (long)MM;
        a.roundC = 1; a.roundA = 1; a.roundB = 1; a.bTrans = 0; a.alpha = 1.f;
        launch_gemm(a, 5);
    }

    // 2) q~[z] = features @ Gt[z]^T  (raw F rounded in smem)
    {
        GArgs a{};
        for (int z = 0; z < 5; ++z) { a.Aarr[z] = features; a.Barr[z] = G + (size_t)z * MM; }
        a.C = QH; a.M = cN; a.Nv = 1024; a.K = 1024;
        a.lda = 1024; a.ldb = 1024; a.ldc = 1024; a.cStride = (long)NE;
        a.roundC = 1; a.roundA = 1; a.roundB = 0; a.bTrans = 0; a.alpha = 1.f;
        launch_gemm(a, 5);
    }

    // 3) stage-1 scores: P[b] = scale * q~_b @ s_b^T  (NT, raw s rounded)
    {
        GArgs a{};
        for (int b = 0; b < 4; ++b) { a.Aarr[b] = QH + (size_t)b * NE; a.Barr[b] = s_in[b]; }
        a.C = P; a.M = cN; a.Nv = TNK; a.K = 1024;
        a.lda = 1024; a.ldb = cE; a.ldc = (long)TNK; a.cStride = (long)cN * TNK;
        a.roundC = 0; a.roundA = 0; a.roundB = 1; a.bTrans = 0; a.alpha = cScale;
        launch_gemm(a, 4);
    }

    // 4) softmax over 34304 segments of 268
    {
        int rows = cB * cN * cS;
        softmax_kernel<<<(rows + 7) / 8, 256>>>(P, rows);
    }

    // 5) U partials: z = b*4+ks; NN over raw s rows [tm][e]
    {
        GArgs a{};
        for (int z = 0; z < 16; ++z) {
            int b = z >> 2, ks = z & 3;
            a.Aarr[z] = P + (size_t)b * cN * TNK + (size_t)ks * KCH;
            a.Barr[z] = s_in[b] + (size_t)ks * KCH * cE;
        }
        a.C = UP; a.M = cN; a.Nv = 1024; a.K = KCH;
        a.lda = TNK; a.ldb = cE; a.ldc = 1024; a.cStride = (long)NE;
        a.roundC = 0; a.roundA = 0; a.roundB = 1; a.bTrans = 1; a.alpha = 1.f;
        launch_gemm(a, 16);
    }
    reduce4<<<dim3((int)(NE / 4 / 256), 1, 4), 256>>>();

    // 6) ms_b = U_b @ wv_b  (NN, raw wv_b rounded)
    {
        GArgs a{};
        for (int b = 0; b < 4; ++b) { a.Aarr[b] = U + (size_t)b * NE; a.Barr[b] = wv_b + (size_t)b * MM; }
        a.C = MSp; a.M = cN; a.Nv = 1024; a.K = 1024;
        a.lda = 1024; a.ldb = 1024; a.ldc = 1024; a.cStride = (long)NE;
        a.roundC = 1; a.roundA = 0; a.roundB = 1; a.bTrans = 1; a.alpha = 1.f;
        launch_gemm(a, 4);
    }

    // 7) stage-2 scores: split-K x4 (NT over ms rows), reduce -> P2
    {
        GArgs a{};
        for (int z = 0; z < 4; ++z) { a.Aarr[z] = QH + 4 * NE + z * 256; a.Barr[z] = MSp + z * 256; }
        a.C = UP; a.M = cN; a.Nv = 4 * cN; a.K = 256;
        a.lda = 1024; a.ldb = 1024; a.ldc = (long)(4 * cN); a.cStride = (long)(cN * 4 * cN);
        a.roundC = 0; a.roundA = 0; a.roundB = 0; a.bTrans = 0; a.alpha = cScale;
        launch_gemm(a, 4);
        const long p4 = (long)(cN * 4 * cN) / 4;
        reduce_k<<<(int)((p4 + 255) / 256), 256>>>((const float4*)UP, (float4*)P2, p4, p4, 0);
    }
    softmax_kernel<<<(4 * cN + 7) / 8, 256>>>(P2, 4 * cN);

    // 8) U2 = P2 @ ms  (NN over ms rows, split-K x4 of 268)
    {
        GArgs a{};
        for (int z = 0; z < 4; ++z) { a.Aarr[z] = P2 + z * 268; a.Barr[z] = MSp + (size_t)z * 268 * 1024; }
        a.C = UP; a.M = cN; a.Nv = 1024; a.K = 268;
        a.lda = 4 * cN; a.ldb = 1024; a.ldc = 1024; a.cStride = (long)NE;
        a.roundC = 0; a.roundA = 0; a.roundB = 0; a.bTrans = 1; a.alpha = 1.f;
        launch_gemm(a, 4);
        const long p4 = (long)NE / 4;
        reduce_k<<<(int)((p4 + 255) / 256), 256>>>((const float4*)UP, (float4*)U2, p4, p4, 1);
    }

    // 9) out = U2 @ wv  (NN, raw wv rounded, split-K x4)
    {
        GArgs a{};
        for (int z = 0; z < 4; ++z) { a.Aarr[z] = U2 + z * 256; a.Barr[z] = wv + (size_t)z * 256 * 1024; }
        a.C = UP; a.M = cN; a.Nv = 1024; a.K = 256;
        a.lda = 1024; a.ldb = 1024; a.ldc = 1024; a.cStride = (long)NE;
        a.roundC = 0; a.roundA = 0; a.roundB = 1; a.bTrans = 1; a.alpha = 1.f;
        launch_gemm(a, 4);
        const long p4 = (long)NE / 4;
        reduce_k<<<(int)((p4 + 255) / 256), 256>>>((const float4*)UP, (float4*)out, p4, p4, 0);
    }
}

// round 13
// speedup vs baseline: 1.2409x; 1.0189x over previous
#include <cuda_runtime.h>
#include <stdint.h>

// ---------------- problem constants ----------------------------------------
constexpr int cN = 268, cS = 32, cE = 1024, cB = 4;
constexpr float cScale = 0.03125f;           // 1/sqrt(1024)
constexpr size_t MM  = 1024ull * 1024ull;
constexpr int   TNK  = cS * cN;              // 8576
constexpr size_t NE  = (size_t)cN * cE;      // 274432

// ---------------- scratch (device globals) ----------------------------------
__device__ __align__(1024) float g_G  [5 * MM];    // Gt = wk*wq^T per branch + stage2
__device__ __align__(1024) float g_qh [5 * NE];    // q-tilde per branch + stage2
__device__ __align__(1024) float g_P  [(size_t)cB * cN * TNK];  // probs [b][n][t*m]
__device__ __align__(1024) float g_UP [32 * NE];   // partials scratch (reused)
__device__ __align__(1024) float g_U  [4 * NE];    // U reduced+rounded
__device__ __align__(1024) float g_ms [4 * NE];    // branch outputs (rounded)
__device__ __align__(1024) float g_P2 [(size_t)cN * 4 * cN];    // stage2 probs [n][t*m]
__device__ __align__(1024) float g_U2 [NE];        // stage2 U (rounded)

// ---------------- PTX helpers -----------------------------------------------
__device__ __forceinline__ uint32_t smem_u32(const void* p) {
    uint32_t a;
    asm("{ .reg .u64 t; cvta.to.shared.u64 t, %1; cvt.u32.u64 %0, t; }" : "=r"(a) : "l"(p));
    return a;
}
__device__ __forceinline__ void cp16(uint32_t dst, const void* src, int nbytes) {
    asm volatile("cp.async.cg.shared.global [%0], [%1], 16, %2;"
                 :: "r"(dst), "l"(src), "r"(nbytes));
}
__device__ __forceinline__ float roundtf(float f) {
    uint32_t r;
    asm("cvt.rna.tf32.f32 %0, %1;" : "=r"(r) : "f"(f));
    return __uint_as_float(r);
}
__device__ __forceinline__ void mma_tf32(float* c, const uint32_t* a, const uint32_t* b) {
    asm volatile(
        "mma.sync.aligned.m16n8k8.row.col.f32.tf32.tf32.f32 "
        "{%0,%1,%2,%3}, {%4,%5,%6,%7}, {%8,%9}, {%0,%1,%2,%3};"
        : "+f"(c[0]), "+f"(c[1]), "+f"(c[2]), "+f"(c[3])
        : "r"(a[0]), "r"(a[1]), "r"(a[2]), "r"(a[3]), "r"(b[0]), "r"(b[1]));
}

// ---------------- tf32 mma.sync GEMM (3-stage cp.async pipeline) -------------
// NT (bTrans=0): C = alpha * A[M,K] * B[Nv,K]^T  (B rows = Nv)
// NN (bTrans=1): C = alpha * A[M,K] * B[K,Nv]    (B rows = K; raw layout)
// Per-batch-z operand pointers come from Aarr/Barr; C = Cbase + z*cStride.
// NOTE: all A/B base pointers and K-split offsets must be 16-byte aligned.
struct GArgs {
    const float* Aarr[32];
    const float* Barr[32];
    float* C;
    int M, Nv, K;
    int lda, ldb; long ldc; long cStride;
    int roundC, roundA, roundB, bTrans;
    float alpha;
};

constexpr int TM_ = 96, TN_ = 128, TK_ = 32;
constexpr int A_F        = TM_ * TK_;               // 3072 floats
constexpr int B_F        = TN_ * TK_;               // 4096 floats
constexpr int STAGE_F    = A_F + B_F;               // 7168 floats (28 KB)
constexpr int NSTAGE     = 3;
constexpr int SMEM_BYTES = NSTAGE * STAGE_F * 4;    // 86016

__device__ __forceinline__ int sw_idx(int r, int c) {
    return r * 32 + ((((c >> 2) ^ (r & 7)) << 2) | (c & 3));
}

__global__ void __launch_bounds__(256, 2) gemm_tc(GArgs g)
{
    extern __shared__ __align__(128) float smem[];
    const uint32_t sbase = smem_u32(smem);
    const int tid  = threadIdx.x;
    const int wid  = tid >> 5, lane = tid & 31;
    const int grp  = lane >> 2, tg = lane & 3;

    const int z = blockIdx.z;
    const float* A = g.Aarr[z];
    const float* B = g.Barr[z];
    float* C = g.C + (long)z * g.cStride;

    const int m0 = blockIdx.y * TM_, n0 = blockIdx.x * TN_;
    const int M = g.M, Nv = g.Nv, K = g.K;
    const long lda = g.lda, ldb = g.ldb;
    const int nchunks = (K + TK_ - 1) / TK_;
    const int bT = g.bTrans;

    const int wrow0 = (wid & 1) * 48;
    const int wcol0 = (wid >> 1) * 32;

    float acc[3][4][4] = {};

    auto load_chunk = [&](int buf, int c) {
        const long k0 = (long)c * TK_;
        const uint32_t sA = sbase + buf * (STAGE_F * 4);
        const uint32_t sB = sA + A_F * 4;
#pragma unroll
        for (int i = 0; i < 3; ++i) {
            int l = tid + i * 256, r = l >> 3, seg = l & 7;
            long grow = m0 + r, gk = k0 + seg * 4;
            bool ok = (grow < M) && (gk < K);
            const float* src = ok ? (A + grow * lda + gk) : A;
            uint32_t off = (uint32_t)(r * 128 + (seg ^ (r & 7)) * 16);
            cp16(sA + off, src, ok ? 16 : 0);
        }
        if (!bT) {
#pragma unroll
            for (int i = 0; i < 4; ++i) {
                int l = tid + i * 256, r = l >> 3, seg = l & 7;
                long grow = n0 + r, gk = k0 + seg * 4;
                bool ok = (grow < Nv) && (gk < K);
                const float* src = ok ? (B + grow * ldb + gk) : B;
                uint32_t off = (uint32_t)(r * 128 + (seg ^ (r & 7)) * 16);
                cp16(sB + off, src, ok ? 16 : 0);
            }
        } else {
            // NN: B tile = 32 k-rows x 128 n-cols; [k][n] smem, n XOR (k&6)<<2
#pragma unroll
            for (int i = 0; i < 4; ++i) {
                int l = tid + i * 256, r = l >> 5, s = l & 31;
                long gk = k0 + r, gcol = n0 + s * 4;
                bool ok = (gk < K) && (gcol < Nv);
                const float* src = ok ? (B + gk * ldb + gcol) : B;
                uint32_t off = (uint32_t)(r * 512 + (((s * 4) ^ ((r & 6) << 2)) << 2));
                cp16(sB + off, src, ok ? 16 : 0);
            }
        }
        asm volatile("cp.async.commit_group;");
    };

    load_chunk(0, 0);
    if (nchunks > 1) load_chunk(1, 1);

    int buf = 0;
    for (int c = 0; c < nchunks; ++c) {
        if (c + 2 < nchunks) {
            int nb = buf + 2; if (nb >= NSTAGE) nb -= NSTAGE;
            load_chunk(nb, c + 2);
            asm volatile("cp.async.wait_group 2;");
        } else if (c + 1 < nchunks) {
            asm volatile("cp.async.wait_group 1;");
        } else {
            asm volatile("cp.async.wait_group 0;");
        }
        __syncthreads();

        if (g.roundA || g.roundB) {
            if (g.roundA) {
                float4* ap = (float4*)(smem + buf * STAGE_F);
#pragma unroll
                for (int q = 0; q < 3; ++q) {
                    float4 v = ap[tid + q * 256];
                    v.x = roundtf(v.x); v.y = roundtf(v.y);
                    v.z = roundtf(v.z); v.w = roundtf(v.w);
                    ap[tid + q * 256] = v;
                }
            }
            if (g.roundB) {
                float4* bp = (float4*)(smem + buf * STAGE_F + A_F);
#pragma unroll
                for (int q = 0; q < 4; ++q) {
                    float4 v = bp[tid + q * 256];
                    v.x = roundtf(v.x); v.y = roundtf(v.y);
                    v.z = roundtf(v.z); v.w = roundtf(v.w);
                    bp[tid + q * 256] = v;
                }
            }
            __syncthreads();
        }

        const float* As = smem + buf * STAGE_F;
        const float* Bs = As + A_F;
#pragma unroll
        for (int ks = 0; ks < 4; ++ks) {
            const int cA = ks * 8 + 2 * tg;
            uint32_t af[3][4], bf[4][2];
#pragma unroll
            for (int mt = 0; mt < 3; ++mt) {
                int r0 = wrow0 + mt * 16 + grp;
                uint2 lo = *(const uint2*)&As[sw_idx(r0,     cA)];
                uint2 hi = *(const uint2*)&As[sw_idx(r0 + 8, cA)];
                af[mt][0] = lo.x; af[mt][1] = hi.x; af[mt][2] = lo.y; af[mt][3] = hi.y;
            }
            if (!bT) {
#pragma unroll
                for (int nt = 0; nt < 4; ++nt) {
                    int rn = wcol0 + nt * 8 + grp;
                    uint2 bb = *(const uint2*)&Bs[sw_idx(rn, cA)];
                    bf[nt][0] = bb.x; bf[nt][1] = bb.y;
                }
            } else {
#pragma unroll
                for (int nt = 0; nt < 4; ++nt) {
                    int rn  = wcol0 + nt * 8 + grp;
                    int nsw = rn ^ ((cA & 6) << 2);
                    bf[nt][0] = *(const uint32_t*)&Bs[cA * TN_ + nsw];
                    bf[nt][1] = *(const uint32_t*)&Bs[(cA + 1) * TN_ + nsw];
                }
            }
#pragma unroll
            for (int mt = 0; mt < 3; ++mt)
#pragma unroll
                for (int nt = 0; nt < 4; ++nt)
                    mma_tf32(acc[mt][nt], af[mt], bf[nt]);
        }
        __syncthreads();
        if (++buf == NSTAGE) buf = 0;
    }

    const float alpha = g.alpha;
    const int rC = g.roundC;
#pragma unroll
    for (int mt = 0; mt < 3; ++mt) {
#pragma unroll
        for (int nt = 0; nt < 4; ++nt) {
            long r0 = m0 + wrow0 + mt * 16 + grp;
            long cc = n0 + wcol0 + nt * 8 + tg * 2;
            if (cc < Nv) {
#pragma unroll
                for (int h = 0; h < 2; ++h) {
                    long rr = r0 + 8 * h;
                    if (rr < M) {
                        float v0 = alpha * acc[mt][nt][2 * h];
                        float v1 = alpha * acc[mt][nt][2 * h + 1];
                        if (rC) { v0 = roundtf(v0); v1 = roundtf(v1); }
                        C[rr * g.ldc + cc]     = v0;
                        C[rr * g.ldc + cc + 1] = v1;
                    }
                }
            }
        }
    }
}

// ---------------- generic batched split-K reduce -----------------------------
// dst[zb][i] = (round?) sum_{p<nparts} src[zb*srcZ4 + p*part4 + i]
__global__ void reduce_n(const float4* __restrict__ src, float4* __restrict__ dst,
                         long part4, long n4, int nparts, int doRound,
                         long srcZ4, long dstZ4)
{
    long i = blockIdx.x * (long)blockDim.x + threadIdx.x;
    if (i >= n4) return;
    const float4* s = src + (long)blockIdx.z * srcZ4 + i;
    float4 r = s[0];
    for (int p = 1; p < nparts; ++p) {
        float4 v = s[(long)p * part4];
        r.x += v.x; r.y += v.y; r.z += v.z; r.w += v.w;
    }
    if (doRound) { r.x = roundtf(r.x); r.y = roundtf(r.y); r.z = roundtf(r.z); r.w = roundtf(r.w); }
    dst[(long)blockIdx.z * dstZ4 + i] = r;
}

// ---------------- softmax (warp per row of 268; rounds output) ---------------
__global__ __launch_bounds__(256) void softmax_kernel(float* __restrict__ base, int rows)
{
    int w = (blockIdx.x * blockDim.x + threadIdx.x) >> 5;
    int lane = threadIdx.x & 31;
    if (w >= rows) return;
    float* row = base + (size_t)w * cN;

    float v[9];
    float m = -1e30f;
#pragma unroll
    for (int j = 0; j < 9; ++j) {
        int c = lane + 32 * j;
        v[j] = (c < cN) ? row[c] : -1e30f;
        m = fmaxf(m, v[j]);
    }
#pragma unroll
    for (int o = 16; o; o >>= 1) m = fmaxf(m, __shfl_xor_sync(0xffffffffu, m, o));
    float s = 0.f;
#pragma unroll
    for (int j = 0; j < 9; ++j) { v[j] = expf(v[j] - m); s += v[j]; }
#pragma unroll
    for (int o = 16; o; o >>= 1) s += __shfl_xor_sync(0xffffffffu, s, o);
    float inv = 1.f / s;
#pragma unroll
    for (int j = 0; j < 9; ++j) {
        int c = lane + 32 * j;
        if (c < cN) row[c] = roundtf(v[j] * inv);
    }
}

// softmax over summed partials: row w = sum_p srcParts[p*partStride + w*cN + :]
__global__ __launch_bounds__(256) void softmax_sum(const float* __restrict__ src,
                                                   float* __restrict__ dst,
                                                   int rows, int nparts, long partStride)
{
    int w = (blockIdx.x * blockDim.x + threadIdx.x) >> 5;
    int lane = threadIdx.x & 31;
    if (w >= rows) return;
    const float* rowp = src + (size_t)w * cN;
    float* rowd = dst + (size_t)w * cN;

    float v[9];
    float m = -1e30f;
#pragma unroll
    for (int j = 0; j < 9; ++j) {
        int c = lane + 32 * j;
        float acc = 0.f;
        if (c < cN)
            for (int p = 0; p < nparts; ++p) acc += rowp[(long)p * partStride + c];
        v[j] = (c < cN) ? acc : -1e30f;
        m = fmaxf(m, v[j]);
    }
#pragma unroll
    for (int o = 16; o; o >>= 1) m = fmaxf(m, __shfl_xor_sync(0xffffffffu, m, o));
    float s = 0.f;
#pragma unroll
    for (int j = 0; j < 9; ++j) { v[j] = expf(v[j] - m); s += v[j]; }
#pragma unroll
    for (int o = 16; o; o >>= 1) s += __shfl_xor_sync(0xffffffffu, s, o);
    float inv = 1.f / s;
#pragma unroll
    for (int j = 0; j < 9; ++j) {
        int c = lane + 32 * j;
        if (c < cN) rowd[c] = roundtf(v[j] * inv);
    }
}

// ---------------- launch -----------------------------------------------------
static inline void launch_gemm(const GArgs& a, int batch)
{
    dim3 grid((a.Nv + TN_ - 1) / TN_, (a.M + TM_ - 1) / TM_, batch);
    gemm_tc<<<grid, 256, SMEM_BYTES>>>(a);
}

extern "C" void kernel_launch(void* const* d_in, const int* in_sizes, int n_in,
                              void* d_out, int out_size)
{
    const float* features = (const float*)d_in[0];
    const float* s_in[4]  = { (const float*)d_in[1], (const float*)d_in[2],
                              (const float*)d_in[3], (const float*)d_in[4] };
    const float* wq_b = (const float*)d_in[5];
    const float* wk_b = (const float*)d_in[6];
    const float* wv_b = (const float*)d_in[7];
    const float* wq   = (const float*)d_in[8];
    const float* wk   = (const float*)d_in[9];
    const float* wv   = (const float*)d_in[10];
    float* out = (float*)d_out;

    cudaFuncSetAttribute(gemm_tc, cudaFuncAttributeMaxDynamicSharedMemorySize, SMEM_BYTES);

    float *G, *QH, *P, *UP, *U, *MSp, *P2, *U2;
    cudaGetSymbolAddress((void**)&G,   g_G);
    cudaGetSymbolAddress((void**)&QH,  g_qh);
    cudaGetSymbolAddress((void**)&P,   g_P);
    cudaGetSymbolAddress((void**)&UP,  g_UP);
    cudaGetSymbolAddress((void**)&U,   g_U);
    cudaGetSymbolAddress((void**)&MSp, g_ms);
    cudaGetSymbolAddress((void**)&P2,  g_P2);
    cudaGetSymbolAddress((void**)&U2,  g_U2);

    const long NE4 = (long)NE / 4;

    // 1) fold Gt[z] = wk_z * wq_z^T  (raw, NT, round in smem + on output)
    {
        GArgs a{};
        for (int z = 0; z < 4; ++z) { a.Aarr[z] = wk_b + (size_t)z * MM; a.Barr[z] = wq_b + (size_t)z * MM; }
        a.Aarr[4] = wk; a.Barr[4] = wq;
        a.C = G; a.M = 1024; a.Nv = 1024; a.K = 1024;
        a.lda = 1024; a.ldb = 1024; a.ldc = 1024; a.cStride = (long)MM;
        a.roundC = 1; a.roundA = 1; a.roundB = 1; a.bTrans = 0; a.alpha = 1.f;
        launch_gemm(a, 5);
    }

    // 2) q~[z] = features @ Gt[z]^T, split-K x2 (K=512 each)
    {
        GArgs a{};
        for (int z = 0; z < 10; ++z) {
            int w = z >> 1, ks = z & 1;
            a.Aarr[z] = features + ks * 512;
            a.Barr[z] = G + (size_t)w * MM + ks * 512;
        }
        a.C = UP; a.M = cN; a.Nv = 1024; a.K = 512;
        a.lda = 1024; a.ldb = 1024; a.ldc = 1024; a.cStride = (long)NE;
        a.roundC = 0; a.roundA = 1; a.roundB = 0; a.bTrans = 0; a.alpha = 1.f;
        launch_gemm(a, 10);
        reduce_n<<<dim3((int)((NE4 + 255) / 256), 1, 5), 256>>>(
            (const float4*)UP, (float4*)QH, NE4, NE4, 2, 1, 2 * NE4, NE4);
    }

    // 3) stage-1 scores: P[b] = scale * q~_b @ s_b^T  (NT, raw s rounded)
    {
        GArgs a{};
        for (int b = 0; b < 4; ++b) { a.Aarr[b] = QH + (size_t)b * NE; a.Barr[b] = s_in[b]; }
        a.C = P; a.M = cN; a.Nv = TNK; a.K = 1024;
        a.lda = 1024; a.ldb = cE; a.ldc = (long)TNK; a.cStride = (long)cN * TNK;
        a.roundC = 0; a.roundA = 0; a.roundB = 1; a.bTrans = 0; a.alpha = cScale;
        launch_gemm(a, 4);
    }

    // 4) softmax over 34304 segments of 268
    {
        int rows = cB * cN * cS;
        softmax_kernel<<<(rows + 7) / 8, 256>>>(P, rows);
    }

    // 5) U: NN over raw s, split-K x8 (K=1072 each), z = b*8+ks
    {
        GArgs a{};
        for (int z = 0; z < 32; ++z) {
            int b = z >> 3, ks = z & 7;
            a.Aarr[z] = P + (size_t)b * cN * TNK + (size_t)ks * 1072;
            a.Barr[z] = s_in[b] + (size_t)ks * 1072 * cE;
        }
        a.C = UP; a.M = cN; a.Nv = 1024; a.K = 1072;
        a.lda = TNK; a.ldb = cE; a.ldc = 1024; a.cStride = (long)NE;
        a.roundC = 0; a.roundA = 0; a.roundB = 1; a.bTrans = 1; a.alpha = 1.f;
        launch_gemm(a, 32);
        reduce_n<<<dim3((int)((NE4 + 255) / 256), 1, 4), 256>>>(
            (const float4*)UP, (float4*)U, NE4, NE4, 8, 1, 8 * NE4, NE4);
    }

    // 6) ms_b = U_b @ wv_b  (NN, raw wv_b rounded), split-K x8 (K=128), z=b*8+ks
    {
        GArgs a{};
        for (int z = 0; z < 32; ++z) {
            int b = z >> 3, ks = z & 7;
            a.Aarr[z] = U + (size_t)b * NE + ks * 128;
            a.Barr[z] = wv_b + (size_t)b * MM + (size_t)ks * 128 * 1024;
        }
        a.C = UP; a.M = cN; a.Nv = 1024; a.K = 128;
        a.lda = 1024; a.ldb = 1024; a.ldc = 1024; a.cStride = (long)NE;
        a.roundC = 0; a.roundA = 0; a.roundB = 1; a.bTrans = 1; a.alpha = 1.f;
        launch_gemm(a, 32);
        reduce_n<<<dim3((int)((NE4 + 255) / 256), 1, 4), 256>>>(
            (const float4*)UP, (float4*)MSp, NE4, NE4, 8, 1, 8 * NE4, NE4);
    }

    // 7) stage-2 scores: split-K x8 (K=128), partial-sum fused into softmax
    {
        GArgs a{};
        for (int z = 0; z < 8; ++z) { a.Aarr[z] = QH + 4 * NE + z * 128; a.Barr[z] = MSp + z * 128; }
        a.C = UP; a.M = cN; a.Nv = 4 * cN; a.K = 128;
        a.lda = 1024; a.ldb = 1024; a.ldc = (long)(4 * cN); a.cStride = (long)(cN * 4 * cN);
        a.roundC = 0; a.roundA = 0; a.roundB = 0; a.bTrans = 0; a.alpha = cScale;
        launch_gemm(a, 8);
        softmax_sum<<<(4 * cN + 7) / 8, 256>>>(UP, P2, 4 * cN, 8, (long)(cN * 4 * cN));
    }

    // 8) U2 = P2 @ ms  (NN, split-K x4 of total K=1072: 268 each, 16B-aligned)
    {
        GArgs a{};
        for (int z = 0; z < 4; ++z) { a.Aarr[z] = P2 + z * 268; a.Barr[z] = MSp + (size_t)z * 268 * 1024; }
        a.C = UP; a.M = cN; a.Nv = 1024; a.K = 268;
        a.lda = 4 * cN; a.ldb = 1024; a.ldc = 1024; a.cStride = (long)NE;
        a.roundC = 0; a.roundA = 0; a.roundB = 0; a.bTrans = 1; a.alpha = 1.f;
        launch_gemm(a, 4);
        reduce_n<<<(int)((NE4 + 255) / 256), 256>>>(
            (const float4*)UP, (float4*)U2, NE4, NE4, 4, 1, 0, 0);
    }

    // 9) out = U2 @ wv  (NN, raw wv rounded, split-K x8, K=128)
    {
        GArgs a{};
        for (int z = 0; z < 8; ++z) { a.Aarr[z] = U2 + z * 128; a.Barr[z] = wv + (size_t)z * 128 * 1024; }
        a.C = UP; a.M = cN; a.Nv = 1024; a.K = 128;
        a.lda = 1024; a.ldb = 1024; a.ldc = 1024; a.cStride = (long)NE;
        a.roundC = 0; a.roundA = 0; a.roundB = 1; a.bTrans = 1; a.alpha = 1.f;
        launch_gemm(a, 8);
        reduce_n<<<(int)((NE4 + 255) / 256), 256>>>(
            (const float4*)UP, (float4*)out, NE4, NE4, 8, 0, 0, 0);
    }
}

// round 14
// speedup vs baseline: 1.4020x; 1.1299x over previous
#include <cuda_runtime.h>
#include <stdint.h>

// ---------------- problem constants ----------------------------------------
constexpr int cN = 268, cS = 32, cE = 1024, cB = 4;
constexpr float cScale = 0.03125f;           // 1/sqrt(1024)
constexpr size_t MM  = 1024ull * 1024ull;
constexpr int   TNK  = cS * cN;              // 8576
constexpr size_t NE  = (size_t)cN * cE;      // 274432
constexpr size_t SNE = (size_t)TNK * cE;     // 8781824

// ---------------- scratch (device globals) ----------------------------------
__device__ __align__(1024) float g_Q  [5 * NE];    // q = F@wq (rounded)
__device__ __align__(1024) float g_S  [4 * SNE];   // rounded snapshots [b][tm][e]
__device__ __align__(1024) float g_qh [5 * NE];    // q~ per branch + stage2
__device__ __align__(1024) float g_P  [(size_t)cB * cN * TNK];  // probs [b][n][t*m]
__device__ __align__(1024) float g_UP [32 * NE];   // partials scratch (reused)
__device__ __align__(1024) float g_U  [4 * NE];    // U reduced+rounded
__device__ __align__(1024) float g_ms [4 * NE];    // branch outputs (rounded)
__device__ __align__(1024) float g_P2 [(size_t)cN * 4 * cN];    // stage2 probs [n][t*m]
__device__ __align__(1024) float g_U2 [NE];        // stage2 U (rounded)

// ---------------- PTX helpers -----------------------------------------------
__device__ __forceinline__ uint32_t smem_u32(const void* p) {
    uint32_t a;
    asm("{ .reg .u64 t; cvta.to.shared.u64 t, %1; cvt.u32.u64 %0, t; }" : "=r"(a) : "l"(p));
    return a;
}
__device__ __forceinline__ void cp16(uint32_t dst, const void* src, int nbytes) {
    asm volatile("cp.async.cg.shared.global [%0], [%1], 16, %2;"
                 :: "r"(dst), "l"(src), "r"(nbytes));
}
__device__ __forceinline__ float roundtf(float f) {
    uint32_t r;
    asm("cvt.rna.tf32.f32 %0, %1;" : "=r"(r) : "f"(f));
    return __uint_as_float(r);
}
__device__ __forceinline__ void mma_tf32(float* c, const uint32_t* a, const uint32_t* b) {
    asm volatile(
        "mma.sync.aligned.m16n8k8.row.col.f32.tf32.tf32.f32 "
        "{%0,%1,%2,%3}, {%4,%5,%6,%7}, {%8,%9}, {%0,%1,%2,%3};"
        : "+f"(c[0]), "+f"(c[1]), "+f"(c[2]), "+f"(c[3])
        : "r"(a[0]), "r"(a[1]), "r"(a[2]), "r"(a[3]), "r"(b[0]), "r"(b[1]));
}

// ---------------- tf32 mma.sync GEMM (3-stage cp.async pipeline) -------------
// NT (bTrans=0): C = alpha * A[M,K] * B[Nv,K]^T  (B rows = Nv)
// NN (bTrans=1): C = alpha * A[M,K] * B[K,Nv]    (B rows = K; raw layout)
// Per-batch-z operand pointers come from Aarr/Barr; C = Cbase + z*cStride.
// NOTE: all A/B base pointers and K-split offsets must be 16-byte aligned.
struct GArgs {
    const float* Aarr[32];
    const float* Barr[32];
    float* C;
    int M, Nv, K;
    int lda, ldb; long ldc; long cStride;
    int roundC, roundA, roundB, bTrans;
    float alpha;
};

constexpr int TM_ = 96, TN_ = 128, TK_ = 32;
constexpr int A_F        = TM_ * TK_;               // 3072 floats
constexpr int B_F        = TN_ * TK_;               // 4096 floats
constexpr int STAGE_F    = A_F + B_F;               // 7168 floats (28 KB)
constexpr int NSTAGE     = 3;
constexpr int SMEM_BYTES = NSTAGE * STAGE_F * 4;    // 86016

__device__ __forceinline__ int sw_idx(int r, int c) {
    return r * 32 + ((((c >> 2) ^ (r & 7)) << 2) | (c & 3));
}

__global__ void __launch_bounds__(256, 2) gemm_tc(GArgs g)
{
    extern __shared__ __align__(128) float smem[];
    const uint32_t sbase = smem_u32(smem);
    const int tid  = threadIdx.x;
    const int wid  = tid >> 5, lane = tid & 31;
    const int grp  = lane >> 2, tg = lane & 3;

    const int z = blockIdx.z;
    const float* A = g.Aarr[z];
    const float* B = g.Barr[z];
    float* C = g.C + (long)z * g.cStride;

    const int m0 = blockIdx.y * TM_, n0 = blockIdx.x * TN_;
    const int M = g.M, Nv = g.Nv, K = g.K;
    const long lda = g.lda, ldb = g.ldb;
    const int nchunks = (K + TK_ - 1) / TK_;
    const int bT = g.bTrans;

    const int wrow0 = (wid & 1) * 48;
    const int wcol0 = (wid >> 1) * 32;

    float acc[3][4][4] = {};

    auto load_chunk = [&](int buf, int c) {
        const long k0 = (long)c * TK_;
        const uint32_t sA = sbase + buf * (STAGE_F * 4);
        const uint32_t sB = sA + A_F * 4;
#pragma unroll
        for (int i = 0; i < 3; ++i) {
            int l = tid + i * 256, r = l >> 3, seg = l & 7;
            long grow = m0 + r, gk = k0 + seg * 4;
            bool ok = (grow < M) && (gk < K);
            const float* src = ok ? (A + grow * lda + gk) : A;
            uint32_t off = (uint32_t)(r * 128 + (seg ^ (r & 7)) * 16);
            cp16(sA + off, src, ok ? 16 : 0);
        }
        if (!bT) {
#pragma unroll
            for (int i = 0; i < 4; ++i) {
                int l = tid + i * 256, r = l >> 3, seg = l & 7;
                long grow = n0 + r, gk = k0 + seg * 4;
                bool ok = (grow < Nv) && (gk < K);
                const float* src = ok ? (B + grow * ldb + gk) : B;
                uint32_t off = (uint32_t)(r * 128 + (seg ^ (r & 7)) * 16);
                cp16(sB + off, src, ok ? 16 : 0);
            }
        } else {
            // NN: B tile = 32 k-rows x 128 n-cols; [k][n] smem, n XOR (k&6)<<2
#pragma unroll
            for (int i = 0; i < 4; ++i) {
                int l = tid + i * 256, r = l >> 5, s = l & 31;
                long gk = k0 + r, gcol = n0 + s * 4;
                bool ok = (gk < K) && (gcol < Nv);
                const float* src = ok ? (B + gk * ldb + gcol) : B;
                uint32_t off = (uint32_t)(r * 512 + (((s * 4) ^ ((r & 6) << 2)) << 2));
                cp16(sB + off, src, ok ? 16 : 0);
            }
        }
        asm volatile("cp.async.commit_group;");
    };

    load_chunk(0, 0);
    if (nchunks > 1) load_chunk(1, 1);

    int buf = 0;
    for (int c = 0; c < nchunks; ++c) {
        if (c + 2 < nchunks) {
            int nb = buf + 2; if (nb >= NSTAGE) nb -= NSTAGE;
            load_chunk(nb, c + 2);
            asm volatile("cp.async.wait_group 2;");
        } else if (c + 1 < nchunks) {
            asm volatile("cp.async.wait_group 1;");
        } else {
            asm volatile("cp.async.wait_group 0;");
        }
        __syncthreads();

        if (g.roundA || g.roundB) {
            if (g.roundA) {
                float4* ap = (float4*)(smem + buf * STAGE_F);
#pragma unroll
                for (int q = 0; q < 3; ++q) {
                    float4 v = ap[tid + q * 256];
                    v.x = roundtf(v.x); v.y = roundtf(v.y);
                    v.z = roundtf(v.z); v.w = roundtf(v.w);
                    ap[tid + q * 256] = v;
                }
            }
            if (g.roundB) {
                float4* bp = (float4*)(smem + buf * STAGE_F + A_F);
#pragma unroll
                for (int q = 0; q < 4; ++q) {
                    float4 v = bp[tid + q * 256];
                    v.x = roundtf(v.x); v.y = roundtf(v.y);
                    v.z = roundtf(v.z); v.w = roundtf(v.w);
                    bp[tid + q * 256] = v;
                }
            }
            __syncthreads();
        }

        const float* As = smem + buf * STAGE_F;
        const float* Bs = As + A_F;
#pragma unroll
        for (int ks = 0; ks < 4; ++ks) {
            const int cA = ks * 8 + 2 * tg;
            uint32_t af[3][4], bf[4][2];
#pragma unroll
            for (int mt = 0; mt < 3; ++mt) {
                int r0 = wrow0 + mt * 16 + grp;
                uint2 lo = *(const uint2*)&As[sw_idx(r0,     cA)];
                uint2 hi = *(const uint2*)&As[sw_idx(r0 + 8, cA)];
                af[mt][0] = lo.x; af[mt][1] = hi.x; af[mt][2] = lo.y; af[mt][3] = hi.y;
            }
            if (!bT) {
#pragma unroll
                for (int nt = 0; nt < 4; ++nt) {
                    int rn = wcol0 + nt * 8 + grp;
                    uint2 bb = *(const uint2*)&Bs[sw_idx(rn, cA)];
                    bf[nt][0] = bb.x; bf[nt][1] = bb.y;
                }
            } else {
#pragma unroll
                for (int nt = 0; nt < 4; ++nt) {
                    int rn  = wcol0 + nt * 8 + grp;
                    int nsw = rn ^ ((cA & 6) << 2);
                    bf[nt][0] = *(const uint32_t*)&Bs[cA * TN_ + nsw];
                    bf[nt][1] = *(const uint32_t*)&Bs[(cA + 1) * TN_ + nsw];
                }
            }
#pragma unroll
            for (int mt = 0; mt < 3; ++mt)
#pragma unroll
                for (int nt = 0; nt < 4; ++nt)
                    mma_tf32(acc[mt][nt], af[mt], bf[nt]);
        }
        __syncthreads();
        if (++buf == NSTAGE) buf = 0;
    }

    const float alpha = g.alpha;
    const int rC = g.roundC;
#pragma unroll
    for (int mt = 0; mt < 3; ++mt) {
#pragma unroll
        for (int nt = 0; nt < 4; ++nt) {
            long r0 = m0 + wrow0 + mt * 16 + grp;
            long cc = n0 + wcol0 + nt * 8 + tg * 2;
            if (cc < Nv) {
#pragma unroll
                for (int h = 0; h < 2; ++h) {
                    long rr = r0 + 8 * h;
                    if (rr < M) {
                        float v0 = alpha * acc[mt][nt][2 * h];
                        float v1 = alpha * acc[mt][nt][2 * h + 1];
                        if (rC) { v0 = roundtf(v0); v1 = roundtf(v1); }
                        C[rr * g.ldc + cc]     = v0;
                        C[rr * g.ldc + cc + 1] = v1;
                    }
                }
            }
        }
    }
}

// ---------------- rounded copy of snapshots ---------------------------------
__global__ void round_s(const float* __restrict__ s1, const float* __restrict__ s2,
                        const float* __restrict__ s3, const float* __restrict__ s4)
{
    const int b = blockIdx.z;
    const float* sp = (b == 0) ? s1 : (b == 1) ? s2 : (b == 2) ? s3 : s4;
    const float4* src = (const float4*)sp;
    float4* dst = (float4*)(g_S + (size_t)b * SNE);
    const long n4 = (long)SNE / 4;
    for (long i = blockIdx.x * (long)blockDim.x + threadIdx.x; i < n4;
         i += (long)gridDim.x * blockDim.x) {
        float4 v = src[i];
        v.x = roundtf(v.x); v.y = roundtf(v.y);
        v.z = roundtf(v.z); v.w = roundtf(v.w);
        dst[i] = v;
    }
}

// ---------------- generic batched split-K reduce -----------------------------
__global__ void reduce_n(const float4* __restrict__ src, float4* __restrict__ dst,
                         long part4, long n4, int nparts, int doRound,
                         long srcZ4, long dstZ4)
{
    long i = blockIdx.x * (long)blockDim.x + threadIdx.x;
    if (i >= n4) return;
    const float4* s = src + (long)blockIdx.z * srcZ4 + i;
    float4 r = s[0];
    for (int p = 1; p < nparts; ++p) {
        float4 v = s[(long)p * part4];
        r.x += v.x; r.y += v.y; r.z += v.z; r.w += v.w;
    }
    if (doRound) { r.x = roundtf(r.x); r.y = roundtf(r.y); r.z = roundtf(r.z); r.w = roundtf(r.w); }
    dst[(long)blockIdx.z * dstZ4 + i] = r;
}

// ---------------- softmax (warp per row of 268; rounds output) ---------------
__global__ __launch_bounds__(256) void softmax_kernel(float* __restrict__ base, int rows)
{
    int w = (blockIdx.x * blockDim.x + threadIdx.x) >> 5;
    int lane = threadIdx.x & 31;
    if (w >= rows) return;
    float* row = base + (size_t)w * cN;

    float v[9];
    float m = -1e30f;
#pragma unroll
    for (int j = 0; j < 9; ++j) {
        int c = lane + 32 * j;
        v[j] = (c < cN) ? row[c] : -1e30f;
        m = fmaxf(m, v[j]);
    }
#pragma unroll
    for (int o = 16; o; o >>= 1) m = fmaxf(m, __shfl_xor_sync(0xffffffffu, m, o));
    float s = 0.f;
#pragma unroll
    for (int j = 0; j < 9; ++j) { v[j] = expf(v[j] - m); s += v[j]; }
#pragma unroll
    for (int o = 16; o; o >>= 1) s += __shfl_xor_sync(0xffffffffu, s, o);
    float inv = 1.f / s;
#pragma unroll
    for (int j = 0; j < 9; ++j) {
        int c = lane + 32 * j;
        if (c < cN) row[c] = roundtf(v[j] * inv);
    }
}

// softmax over summed partials: row w = sum_p srcParts[p*partStride + w*cN + :]
__global__ __launch_bounds__(256) void softmax_sum(const float* __restrict__ src,
                                                   float* __restrict__ dst,
                                                   int rows, int nparts, long partStride)
{
    int w = (blockIdx.x * blockDim.x + threadIdx.x) >> 5;
    int lane = threadIdx.x & 31;
    if (w >= rows) return;
    const float* rowp = src + (size_t)w * cN;
    float* rowd = dst + (size_t)w * cN;

    float v[9];
    float m = -1e30f;
#pragma unroll
    for (int j = 0; j < 9; ++j) {
        int c = lane + 32 * j;
        float acc = 0.f;
        if (c < cN)
            for (int p = 0; p < nparts; ++p) acc += rowp[(long)p * partStride + c];
        v[j] = (c < cN) ? acc : -1e30f;
        m = fmaxf(m, v[j]);
    }
#pragma unroll
    for (int o = 16; o; o >>= 1) m = fmaxf(m, __shfl_xor_sync(0xffffffffu, m, o));
    float s = 0.f;
#pragma unroll
    for (int j = 0; j < 9; ++j) { v[j] = expf(v[j] - m); s += v[j]; }
#pragma unroll
    for (int o = 16; o; o >>= 1) s += __shfl_xor_sync(0xffffffffu, s, o);
    float inv = 1.f / s;
#pragma unroll
    for (int j = 0; j < 9; ++j) {
        int c = lane + 32 * j;
        if (c < cN) rowd[c] = roundtf(v[j] * inv);
    }
}

// ---------------- launch -----------------------------------------------------
static inline void launch_gemm(const GArgs& a, int batch)
{
    dim3 grid((a.Nv + TN_ - 1) / TN_, (a.M + TM_ - 1) / TM_, batch);
    gemm_tc<<<grid, 256, SMEM_BYTES>>>(a);
}

extern "C" void kernel_launch(void* const* d_in, const int* in_sizes, int n_in,
                              void* d_out, int out_size)
{
    const float* features = (const float*)d_in[0];
    const float* s1 = (const float*)d_in[1];
    const float* s2 = (const float*)d_in[2];
    const float* s3 = (const float*)d_in[3];
    const float* s4 = (const float*)d_in[4];
    const float* wq_b = (const float*)d_in[5];
    const float* wk_b = (const float*)d_in[6];
    const float* wv_b = (const float*)d_in[7];
    const float* wq   = (const float*)d_in[8];
    const float* wk   = (const float*)d_in[9];
    const float* wv   = (const float*)d_in[10];
    float* out = (float*)d_out;

    cudaFuncSetAttribute(gemm_tc, cudaFuncAttributeMaxDynamicSharedMemorySize, SMEM_BYTES);

    float *Q, *S, *QH, *P, *UP, *U, *MSp, *P2, *U2;
    cudaGetSymbolAddress((void**)&Q,   g_Q);
    cudaGetSymbolAddress((void**)&S,   g_S);
    cudaGetSymbolAddress((void**)&QH,  g_qh);
    cudaGetSymbolAddress((void**)&P,   g_P);
    cudaGetSymbolAddress((void**)&UP,  g_UP);
    cudaGetSymbolAddress((void**)&U,   g_U);
    cudaGetSymbolAddress((void**)&MSp, g_ms);
    cudaGetSymbolAddress((void**)&P2,  g_P2);
    cudaGetSymbolAddress((void**)&U2,  g_U2);

    const long NE4 = (long)NE / 4;

    // 0) pre-round snapshots (serves scores NT and U NN)
    round_s<<<dim3(512, 1, 4), 256>>>(s1, s2, s3, s4);

    // 1) q[z] = F @ wq_z  (NN, raw, rounded in smem), split-K x2 -> g_Q
    {
        GArgs a{};
        for (int z = 0; z < 10; ++z) {
            int w = z >> 1, ks = z & 1;
            const float* wqp = (w < 4) ? wq_b + (size_t)w * MM : wq;
            a.Aarr[z] = features + ks * 512;
            a.Barr[z] = wqp + (size_t)ks * 512 * 1024;
        }
        a.C = UP; a.M = cN; a.Nv = 1024; a.K = 512;
        a.lda = 1024; a.ldb = 1024; a.ldc = 1024; a.cStride = (long)NE;
        a.roundC = 0; a.roundA = 1; a.roundB = 1; a.bTrans = 1; a.alpha = 1.f;
        launch_gemm(a, 10);
        reduce_n<<<dim3((int)((NE4 + 255) / 256), 1, 5), 256>>>(
            (const float4*)UP, (float4*)Q, NE4, NE4, 2, 1, 2 * NE4, NE4);
    }

    // 2) q~[z] = q_z @ wk_z^T  (NT: B[e][f] = wk rows e), split-K x2 -> g_qh
    {
        GArgs a{};
        for (int z = 0; z < 10; ++z) {
            int w = z >> 1, ks = z & 1;
            const float* wkp = (w < 4) ? wk_b + (size_t)w * MM : wk;
            a.Aarr[z] = Q + (size_t)w * NE + ks * 512;
            a.Barr[z] = wkp + ks * 512;
        }
        a.C = UP; a.M = cN; a.Nv = 1024; a.K = 512;
        a.lda = 1024; a.ldb = 1024; a.ldc = 1024; a.cStride = (long)NE;
        a.roundC = 0; a.roundA = 0; a.roundB = 1; a.bTrans = 0; a.alpha = 1.f;
        launch_gemm(a, 10);
        reduce_n<<<dim3((int)((NE4 + 255) / 256), 1, 5), 256>>>(
            (const float4*)UP, (float4*)QH, NE4, NE4, 2, 1, 2 * NE4, NE4);
    }

    // 3) stage-1 scores: P[b] = scale * q~_b @ S_b^T  (NT, pre-rounded S)
    {
        GArgs a{};
        for (int b = 0; b < 4; ++b) { a.Aarr[b] = QH + (size_t)b * NE; a.Barr[b] = S + (size_t)b * SNE; }
        a.C = P; a.M = cN; a.Nv = TNK; a.K = 1024;
        a.lda = 1024; a.ldb = cE; a.ldc = (long)TNK; a.cStride = (long)cN * TNK;
        a.roundC = 0; a.roundA = 0; a.roundB = 0; a.bTrans = 0; a.alpha = cScale;
        launch_gemm(a, 4);
    }

    // 4) softmax over 34304 segments of 268
    {
        int rows = cB * cN * cS;
        softmax_kernel<<<(rows + 7) / 8, 256>>>(P, rows);
    }

    // 5) U: NN over pre-rounded S, split-K x8 (K=1072 each), z = b*8+ks
    {
        GArgs a{};
        for (int z = 0; z < 32; ++z) {
            int b = z >> 3, ks = z & 7;
            a.Aarr[z] = P + (size_t)b * cN * TNK + (size_t)ks * 1072;
            a.Barr[z] = S + (size_t)b * SNE + (size_t)ks * 1072 * cE;
        }
        a.C = UP; a.M = cN; a.Nv = 1024; a.K = 1072;
        a.lda = TNK; a.ldb = cE; a.ldc = 1024; a.cStride = (long)NE;
        a.roundC = 0; a.roundA = 0; a.roundB = 0; a.bTrans = 1; a.alpha = 1.f;
        launch_gemm(a, 32);
        reduce_n<<<dim3((int)((NE4 + 255) / 256), 1, 4), 256>>>(
            (const float4*)UP, (float4*)U, NE4, NE4, 8, 1, 8 * NE4, NE4);
    }

    // 6) ms_b = U_b @ wv_b  (NN, raw wv_b rounded), split-K x8 (K=128), z=b*8+ks
    {
        GArgs a{};
        for (int z = 0; z < 32; ++z) {
            int b = z >> 3, ks = z & 7;
            a.Aarr[z] = U + (size_t)b * NE + ks * 128;
            a.Barr[z] = wv_b + (size_t)b * MM + (size_t)ks * 128 * 1024;
        }
        a.C = UP; a.M = cN; a.Nv = 1024; a.K = 128;
        a.lda = 1024; a.ldb = 1024; a.ldc = 1024; a.cStride = (long)NE;
        a.roundC = 0; a.roundA = 0; a.roundB = 1; a.bTrans = 1; a.alpha = 1.f;
        launch_gemm(a, 32);
        reduce_n<<<dim3((int)((NE4 + 255) / 256), 1, 4), 256>>>(
            (const float4*)UP, (float4*)MSp, NE4, NE4, 8, 1, 8 * NE4, NE4);
    }

    // 7) stage-2 scores: split-K x8 (K=128), partial-sum fused into softmax
    {
        GArgs a{};
        for (int z = 0; z < 8; ++z) { a.Aarr[z] = QH + 4 * NE + z * 128; a.Barr[z] = MSp + z * 128; }
        a.C = UP; a.M = cN; a.Nv = 4 * cN; a.K = 128;
        a.lda = 1024; a.ldb = 1024; a.ldc = (long)(4 * cN); a.cStride = (long)(cN * 4 * cN);
        a.roundC = 0; a.roundA = 0; a.roundB = 0; a.bTrans = 0; a.alpha = cScale;
        launch_gemm(a, 8);
        softmax_sum<<<(4 * cN + 7) / 8, 256>>>(UP, P2, 4 * cN, 8, (long)(cN * 4 * cN));
    }

    // 8) U2 = P2 @ ms  (NN, split-K x4 of total K=1072: 268 each, 16B-aligned)
    {
        GArgs a{};
        for (int z = 0; z < 4; ++z) { a.Aarr[z] = P2 + z * 268; a.Barr[z] = MSp + (size_t)z * 268 * 1024; }
        a.C = UP; a.M = cN; a.Nv = 1024; a.K = 268;
        a.lda = 4 * cN; a.ldb = 1024; a.ldc = 1024; a.cStride = (long)NE;
        a.roundC = 0; a.roundA = 0; a.roundB = 0; a.bTrans = 1; a.alpha = 1.f;
        launch_gemm(a, 4);
        reduce_n<<<(int)((NE4 + 255) / 256), 256>>>(
            (const float4*)UP, (float4*)U2, NE4, NE4, 4, 1, 0, 0);
    }

    // 9) out = U2 @ wv  (NN, raw wv rounded, split-K x8, K=128)
    {
        GArgs a{};
        for (int z = 0; z < 8; ++z) { a.Aarr[z] = U2 + z * 128; a.Barr[z] = wv + (size_t)z * 128 * 1024; }
        a.C = UP; a.M = cN; a.Nv = 1024; a.K = 128;
        a.lda = 1024; a.ldb = 1024; a.ldc = 1024; a.cStride = (long)NE;
        a.roundC = 0; a.roundA = 0; a.roundB = 1; a.bTrans = 1; a.alpha = 1.f;
        launch_gemm(a, 8);
        reduce_n<<<(int)((NE4 + 255) / 256), 256>>>(
            (const float4*)UP, (float4*)out, NE4, NE4, 8, 0, 0, 0);
    }
}

// round 15
// speedup vs baseline: 1.5250x; 1.0877x over previous
#include <cuda_runtime.h>
#include <stdint.h>

// ---------------- problem constants ----------------------------------------
constexpr int cN = 268, cS = 32, cE = 1024, cB = 4;
constexpr float cScale = 0.03125f;           // 1/sqrt(1024)
constexpr size_t MM  = 1024ull * 1024ull;
constexpr int   TNK  = cS * cN;              // 8576
constexpr size_t NE  = (size_t)cN * cE;      // 274432
constexpr size_t SNE = (size_t)TNK * cE;     // 8781824

// ---------------- scratch (device globals) ----------------------------------
__device__ __align__(1024) float g_Q  [5 * NE];    // q = F@wq (rounded)
__device__ __align__(1024) float g_S  [4 * SNE];   // rounded snapshots [b][tm][e]
__device__ __align__(1024) float g_qh [5 * NE];    // q~ per branch + stage2
__device__ __align__(1024) float g_P  [(size_t)cB * cN * TNK];  // probs [b][n][t*m]
__device__ __align__(1024) float g_UP [32 * NE];   // partials scratch (reused)
__device__ __align__(1024) float g_U  [4 * NE];    // U reduced+rounded
__device__ __align__(1024) float g_ms [4 * NE];    // branch outputs (rounded)
__device__ __align__(1024) float g_P2 [(size_t)cN * 4 * cN];    // stage2 probs [n][t*m]
__device__ __align__(1024) float g_U2 [NE];        // stage2 U (rounded)

// ---------------- PTX helpers -----------------------------------------------
__device__ __forceinline__ uint32_t smem_u32(const void* p) {
    uint32_t a;
    asm("{ .reg .u64 t; cvta.to.shared.u64 t, %1; cvt.u32.u64 %0, t; }" : "=r"(a) : "l"(p));
    return a;
}
__device__ __forceinline__ void cp16(uint32_t dst, const void* src, int nbytes) {
    asm volatile("cp.async.cg.shared.global [%0], [%1], 16, %2;"
                 :: "r"(dst), "l"(src), "r"(nbytes));
}
__device__ __forceinline__ float roundtf(float f) {
    uint32_t r;
    asm("cvt.rna.tf32.f32 %0, %1;" : "=r"(r) : "f"(f));
    return __uint_as_float(r);
}
__device__ __forceinline__ void mma_tf32(float* c, const uint32_t* a, const uint32_t* b) {
    asm volatile(
        "mma.sync.aligned.m16n8k8.row.col.f32.tf32.tf32.f32 "
        "{%0,%1,%2,%3}, {%4,%5,%6,%7}, {%8,%9}, {%0,%1,%2,%3};"
        : "+f"(c[0]), "+f"(c[1]), "+f"(c[2]), "+f"(c[3])
        : "r"(a[0]), "r"(a[1]), "r"(a[2]), "r"(a[3]), "r"(b[0]), "r"(b[1]));
}

// ---------------- tf32 mma.sync GEMM (3-stage cp.async pipeline) -------------
// NT (bTrans=0): C = alpha * A[M,K] * B[Nv,K]^T  (B rows = Nv)
// NN (bTrans=1): C = alpha * A[M,K] * B[K,Nv]    (B rows = K; raw layout)
// Per-batch-z operand pointers come from Aarr/Barr; C = Cbase + z*cStride.
// NOTE: all A/B base pointers and K-split offsets must be 16-byte aligned.
//
// k-permutation (pair form): HW (slice 2p, col t) <- logical k 16p+4t,
// (2p, t+4) <- +1, (2p+1, t) <- +2, (2p+1, t+4) <- +3. Applied to A and B
// identically (dot-product invariant). One lds.128 feeds 2 slices.
struct GArgs {
    const float* Aarr[32];
    const float* Barr[32];
    float* C;
    int M, Nv, K;
    int lda, ldb; long ldc; long cStride;
    int roundC, roundA, roundB, bTrans;
    float alpha;
};

constexpr int TM_ = 96, TN_ = 128, TK_ = 32;
constexpr int A_F        = TM_ * TK_;               // 3072 floats
constexpr int B_F        = TN_ * TK_;               // 4096 floats
constexpr int STAGE_F    = A_F + B_F;               // 7168 floats (28 KB)
constexpr int NSTAGE     = 3;
constexpr int SMEM_BYTES = NSTAGE * STAGE_F * 4;    // 86016

// sw3: permutation of r&7 such that 8-lane lds.128 phases (grp{0,1} x tg{0..3})
// cover all 8 16B-groups.  sw3(x) = ((x&1)<<2) | (x>>1)
__device__ __forceinline__ int sw3f(int x) { return ((x & 1) << 2) | (x >> 1); }

__global__ void __launch_bounds__(256, 2) gemm_tc(GArgs g)
{
    extern __shared__ __align__(128) float smem[];
    const uint32_t sbase = smem_u32(smem);
    const int tid  = threadIdx.x;
    const int wid  = tid >> 5, lane = tid & 31;
    const int grp  = lane >> 2, tg = lane & 3;
    const int sw3g = sw3f(grp);

    const int z = blockIdx.z;
    const float* A = g.Aarr[z];
    const float* B = g.Barr[z];
    float* C = g.C + (long)z * g.cStride;

    const int m0 = blockIdx.y * TM_, n0 = blockIdx.x * TN_;
    const int M = g.M, Nv = g.Nv, K = g.K;
    const long lda = g.lda, ldb = g.ldb;
    const int nchunks = (K + TK_ - 1) / TK_;
    const int bT = g.bTrans;

    const int wrow0 = (wid & 1) * 48;
    const int wcol0 = (wid >> 1) * 32;

    float acc[3][4][4] = {};

    auto load_chunk = [&](int buf, int c) {
        const long k0 = (long)c * TK_;
        const uint32_t sA = sbase + buf * (STAGE_F * 4);
        const uint32_t sB = sA + A_F * 4;
#pragma unroll
        for (int i = 0; i < 3; ++i) {
            int l = tid + i * 256, r = l >> 3, seg = l & 7;
            long grow = m0 + r, gk = k0 + seg * 4;
            bool ok = (grow < M) && (gk < K);
            const float* src = ok ? (A + grow * lda + gk) : A;
            uint32_t off = (uint32_t)(r * 128 + (seg ^ sw3f(r & 7)) * 16);
            cp16(sA + off, src, ok ? 16 : 0);
        }
        if (!bT) {
#pragma unroll
            for (int i = 0; i < 4; ++i) {
                int l = tid + i * 256, r = l >> 3, seg = l & 7;
                long grow = n0 + r, gk = k0 + seg * 4;
                bool ok = (grow < Nv) && (gk < K);
                const float* src = ok ? (B + grow * ldb + gk) : B;
                uint32_t off = (uint32_t)(r * 128 + (seg ^ sw3f(r & 7)) * 16);
                cp16(sB + off, src, ok ? 16 : 0);
            }
        } else {
            // NN: B tile = 32 k-rows x 128 n-cols; [k][n] smem,
            // col s*4 XOR shift, shift = ((r>>2)&3)<<3
#pragma unroll
            for (int i = 0; i < 4; ++i) {
                int l = tid + i * 256, r = l >> 5, s = l & 31;
                long gk = k0 + r, gcol = n0 + s * 4;
                bool ok = (gk < K) && (gcol < Nv);
                const float* src = ok ? (B + gk * ldb + gcol) : B;
                uint32_t off = (uint32_t)(r * 512 + (((s * 4) ^ (((r >> 2) & 3) << 3)) << 2));
                cp16(sB + off, src, ok ? 16 : 0);
            }
        }
        asm volatile("cp.async.commit_group;");
    };

    load_chunk(0, 0);
    if (nchunks > 1) load_chunk(1, 1);

    int buf = 0;
    for (int c = 0; c < nchunks; ++c) {
        if (c + 2 < nchunks) {
            int nb = buf + 2; if (nb >= NSTAGE) nb -= NSTAGE;
            load_chunk(nb, c + 2);
            asm volatile("cp.async.wait_group 2;");
        } else if (c + 1 < nchunks) {
            asm volatile("cp.async.wait_group 1;");
        } else {
            asm volatile("cp.async.wait_group 0;");
        }
        __syncthreads();

        if (g.roundA || g.roundB) {
            if (g.roundA) {
                float4* ap = (float4*)(smem + buf * STAGE_F);
#pragma unroll
                for (int q = 0; q < 3; ++q) {
                    float4 v = ap[tid + q * 256];
                    v.x = roundtf(v.x); v.y = roundtf(v.y);
                    v.z = roundtf(v.z); v.w = roundtf(v.w);
                    ap[tid + q * 256] = v;
                }
            }
            if (g.roundB) {
                float4* bp = (float4*)(smem + buf * STAGE_F + A_F);
#pragma unroll
                for (int q = 0; q < 4; ++q) {
                    float4 v = bp[tid + q * 256];
                    v.x = roundtf(v.x); v.y = roundtf(v.y);
                    v.z = roundtf(v.z); v.w = roundtf(v.w);
                    bp[tid + q * 256] = v;
                }
            }
            __syncthreads();
        }

        const float* As = smem + buf * STAGE_F;
        const float* Bs = As + A_F;

#pragma unroll
        for (int p = 0; p < 2; ++p) {
            const int cs = ((4 * p + tg) ^ sw3g) << 2;   // float offset of 16B seg
            uint4 a0[3], a8[3];
#pragma unroll
            for (int mt = 0; mt < 3; ++mt) {
                int r0 = wrow0 + mt * 16 + grp;
                a0[mt] = *(const uint4*)&As[r0 * 32 + cs];
                a8[mt] = *(const uint4*)&As[(r0 + 8) * 32 + cs];
            }
            uint32_t bfr[4][4];
            if (!bT) {
#pragma unroll
                for (int nt = 0; nt < 4; ++nt) {
                    int rn = wcol0 + nt * 8 + grp;
                    uint4 w = *(const uint4*)&Bs[rn * 32 + cs];
                    bfr[nt][0] = w.x; bfr[nt][1] = w.y; bfr[nt][2] = w.z; bfr[nt][3] = w.w;
                }
            } else {
                const int rbase = 16 * p + 4 * tg;
#pragma unroll
                for (int nt = 0; nt < 4; ++nt) {
                    int nsw = (wcol0 + nt * 8 + grp) ^ (8 * tg);
                    bfr[nt][0] = *(const uint32_t*)&Bs[(rbase + 0) * TN_ + nsw];
                    bfr[nt][1] = *(const uint32_t*)&Bs[(rbase + 1) * TN_ + nsw];
                    bfr[nt][2] = *(const uint32_t*)&Bs[(rbase + 2) * TN_ + nsw];
                    bfr[nt][3] = *(const uint32_t*)&Bs[(rbase + 3) * TN_ + nsw];
                }
            }
            // slice even (HW slice 2p): logical k = 16p + 4t (+1 for t+4)
#pragma unroll
            for (int mt = 0; mt < 3; ++mt) {
                uint32_t af[4] = { a0[mt].x, a8[mt].x, a0[mt].y, a8[mt].y };
#pragma unroll
                for (int nt = 0; nt < 4; ++nt) {
                    uint32_t bb[2] = { bfr[nt][0], bfr[nt][1] };
                    mma_tf32(acc[mt][nt], af, bb);
                }
            }
            // slice odd (HW slice 2p+1): logical k = 16p + 4t + 2 (+3)
#pragma unroll
            for (int mt = 0; mt < 3; ++mt) {
                uint32_t af[4] = { a0[mt].z, a8[mt].z, a0[mt].w, a8[mt].w };
#pragma unroll
                for (int nt = 0; nt < 4; ++nt) {
                    uint32_t bb[2] = { bfr[nt][2], bfr[nt][3] };
                    mma_tf32(acc[mt][nt], af, bb);
                }
            }
        }
        __syncthreads();
        if (++buf == NSTAGE) buf = 0;
    }

    const float alpha = g.alpha;
    const int rC = g.roundC;
#pragma unroll
    for (int mt = 0; mt < 3; ++mt) {
#pragma unroll
        for (int nt = 0; nt < 4; ++nt) {
            long r0 = m0 + wrow0 + mt * 16 + grp;
            long cc = n0 + wcol0 + nt * 8 + tg * 2;
            if (cc < Nv) {
#pragma unroll
                for (int h = 0; h < 2; ++h) {
                    long rr = r0 + 8 * h;
                    if (rr < M) {
                        float v0 = alpha * acc[mt][nt][2 * h];
                        float v1 = alpha * acc[mt][nt][2 * h + 1];
                        if (rC) { v0 = roundtf(v0); v1 = roundtf(v1); }
                        C[rr * g.ldc + cc]     = v0;
                        C[rr * g.ldc + cc + 1] = v1;
                    }
                }
            }
        }
    }
}

// ---------------- rounded copy of snapshots ---------------------------------
__global__ void round_s(const float* __restrict__ s1, const float* __restrict__ s2,
                        const float* __restrict__ s3, const float* __restrict__ s4)
{
    const int b = blockIdx.z;
    const float* sp = (b == 0) ? s1 : (b == 1) ? s2 : (b == 2) ? s3 : s4;
    const float4* src = (const float4*)sp;
    float4* dst = (float4*)(g_S + (size_t)b * SNE);
    const long n4 = (long)SNE / 4;
    for (long i = blockIdx.x * (long)blockDim.x + threadIdx.x; i < n4;
         i += (long)gridDim.x * blockDim.x) {
        float4 v = src[i];
        v.x = roundtf(v.x); v.y = roundtf(v.y);
        v.z = roundtf(v.z); v.w = roundtf(v.w);
        dst[i] = v;
    }
}

// ---------------- generic batched split-K reduce -----------------------------
__global__ void reduce_n(const float4* __restrict__ src, float4* __restrict__ dst,
                         long part4, long n4, int nparts, int doRound,
                         long srcZ4, long dstZ4)
{
    long i = blockIdx.x * (long)blockDim.x + threadIdx.x;
    if (i >= n4) return;
    const float4* s = src + (long)blockIdx.z * srcZ4 + i;
    float4 r = s[0];
    for (int p = 1; p < nparts; ++p) {
        float4 v = s[(long)p * part4];
        r.x += v.x; r.y += v.y; r.z += v.z; r.w += v.w;
    }
    if (doRound) { r.x = roundtf(r.x); r.y = roundtf(r.y); r.z = roundtf(r.z); r.w = roundtf(r.w); }
    dst[(long)blockIdx.z * dstZ4 + i] = r;
}

// ---------------- softmax (warp per row of 268; rounds output) ---------------
__global__ __launch_bounds__(256) void softmax_kernel(float* __restrict__ base, int rows)
{
    int w = (blockIdx.x * blockDim.x + threadIdx.x) >> 5;
    int lane = threadIdx.x & 31;
    if (w >= rows) return;
    float* row = base + (size_t)w * cN;

    float v[9];
    float m = -1e30f;
#pragma unroll
    for (int j = 0; j < 9; ++j) {
        int c = lane + 32 * j;
        v[j] = (c < cN) ? row[c] : -1e30f;
        m = fmaxf(m, v[j]);
    }
#pragma unroll
    for (int o = 16; o; o >>= 1) m = fmaxf(m, __shfl_xor_sync(0xffffffffu, m, o));
    float s = 0.f;
#pragma unroll
    for (int j = 0; j < 9; ++j) { v[j] = expf(v[j] - m); s += v[j]; }
#pragma unroll
    for (int o = 16; o; o >>= 1) s += __shfl_xor_sync(0xffffffffu, s, o);
    float inv = 1.f / s;
#pragma unroll
    for (int j = 0; j < 9; ++j) {
        int c = lane + 32 * j;
        if (c < cN) row[c] = roundtf(v[j] * inv);
    }
}

// softmax over summed partials: row w = sum_p srcParts[p*partStride + w*cN + :]
__global__ __launch_bounds__(256) void softmax_sum(const float* __restrict__ src,
                                                   float* __restrict__ dst,
                                                   int rows, int nparts, long partStride)
{
    int w = (blockIdx.x * blockDim.x + threadIdx.x) >> 5;
    int lane = threadIdx.x & 31;
    if (w >= rows) return;
    const float* rowp = src + (size_t)w * cN;
    float* rowd = dst + (size_t)w * cN;

    float v[9];
    float m = -1e30f;
#pragma unroll
    for (int j = 0; j < 9; ++j) {
        int c = lane + 32 * j;
        float acc = 0.f;
        if (c < cN)
            for (int p = 0; p < nparts; ++p) acc += rowp[(long)p * partStride + c];
        v[j] = (c < cN) ? acc : -1e30f;
        m = fmaxf(m, v[j]);
    }
#pragma unroll
    for (int o = 16; o; o >>= 1) m = fmaxf(m, __shfl_xor_sync(0xffffffffu, m, o));
    float s = 0.f;
#pragma unroll
    for (int j = 0; j < 9; ++j) { v[j] = expf(v[j] - m); s += v[j]; }
#pragma unroll
    for (int o = 16; o; o >>= 1) s += __shfl_xor_sync(0xffffffffu, s, o);
    float inv = 1.f / s;
#pragma unroll
    for (int j = 0; j < 9; ++j) {
        int c = lane + 32 * j;
        if (c < cN) rowd[c] = roundtf(v[j] * inv);
    }
}

// ---------------- launch -----------------------------------------------------
static inline void launch_gemm(const GArgs& a, int batch)
{
    dim3 grid((a.Nv + TN_ - 1) / TN_, (a.M + TM_ - 1) / TM_, batch);
    gemm_tc<<<grid, 256, SMEM_BYTES>>>(a);
}

extern "C" void kernel_launch(void* const* d_in, const int* in_sizes, int n_in,
                              void* d_out, int out_size)
{
    const float* features = (const float*)d_in[0];
    const float* s1 = (const float*)d_in[1];
    const float* s2 = (const float*)d_in[2];
    const float* s3 = (const float*)d_in[3];
    const float* s4 = (const float*)d_in[4];
    const float* wq_b = (const float*)d_in[5];
    const float* wk_b = (const float*)d_in[6];
    const float* wv_b = (const float*)d_in[7];
    const float* wq   = (const float*)d_in[8];
    const float* wk   = (const float*)d_in[9];
    const float* wv   = (const float*)d_in[10];
    float* out = (float*)d_out;

    cudaFuncSetAttribute(gemm_tc, cudaFuncAttributeMaxDynamicSharedMemorySize, SMEM_BYTES);

    float *Q, *S, *QH, *P, *UP, *U, *MSp, *P2, *U2;
    cudaGetSymbolAddress((void**)&Q,   g_Q);
    cudaGetSymbolAddress((void**)&S,   g_S);
    cudaGetSymbolAddress((void**)&QH,  g_qh);
    cudaGetSymbolAddress((void**)&P,   g_P);
    cudaGetSymbolAddress((void**)&UP,  g_UP);
    cudaGetSymbolAddress((void**)&U,   g_U);
    cudaGetSymbolAddress((void**)&MSp, g_ms);
    cudaGetSymbolAddress((void**)&P2,  g_P2);
    cudaGetSymbolAddress((void**)&U2,  g_U2);

    const long NE4 = (long)NE / 4;

    // 0) pre-round snapshots (serves scores NT and U NN)
    round_s<<<dim3(512, 1, 4), 256>>>(s1, s2, s3, s4);

    // 1) q[z] = F @ wq_z  (NN, raw, rounded in smem), split-K x2 -> g_Q
    {
        GArgs a{};
        for (int z = 0; z < 10; ++z) {
            int w = z >> 1, ks = z & 1;
            const float* wqp = (w < 4) ? wq_b + (size_t)w * MM : wq;
            a.Aarr[z] = features + ks * 512;
            a.Barr[z] = wqp + (size_t)ks * 512 * 1024;
        }
        a.C = UP; a.M = cN; a.Nv = 1024; a.K = 512;
        a.lda = 1024; a.ldb = 1024; a.ldc = 1024; a.cStride = (long)NE;
        a.roundC = 0; a.roundA = 1; a.roundB = 1; a.bTrans = 1; a.alpha = 1.f;
        launch_gemm(a, 10);
        reduce_n<<<dim3((int)((NE4 + 255) / 256), 1, 5), 256>>>(
            (const float4*)UP, (float4*)Q, NE4, NE4, 2, 1, 2 * NE4, NE4);
    }

    // 2) q~[z] = q_z @ wk_z^T  (NT: B[e][f] = wk rows e), split-K x2 -> g_qh
    {
        GArgs a{};
        for (int z = 0; z < 10; ++z) {
            int w = z >> 1, ks = z & 1;
            const float* wkp = (w < 4) ? wk_b + (size_t)w * MM : wk;
            a.Aarr[z] = Q + (size_t)w * NE + ks * 512;
            a.Barr[z] = wkp + ks * 512;
        }
        a.C = UP; a.M = cN; a.Nv = 1024; a.K = 512;
        a.lda = 1024; a.ldb = 1024; a.ldc = 1024; a.cStride = (long)NE;
        a.roundC = 0; a.roundA = 0; a.roundB = 1; a.bTrans = 0; a.alpha = 1.f;
        launch_gemm(a, 10);
        reduce_n<<<dim3((int)((NE4 + 255) / 256), 1, 5), 256>>>(
            (const float4*)UP, (float4*)QH, NE4, NE4, 2, 1, 2 * NE4, NE4);
    }

    // 3) stage-1 scores: P[b] = scale * q~_b @ S_b^T  (NT, pre-rounded S)
    {
        GArgs a{};
        for (int b = 0; b < 4; ++b) { a.Aarr[b] = QH + (size_t)b * NE; a.Barr[b] = S + (size_t)b * SNE; }
        a.C = P; a.M = cN; a.Nv = TNK; a.K = 1024;
        a.lda = 1024; a.ldb = cE; a.ldc = (long)TNK; a.cStride = (long)cN * TNK;
        a.roundC = 0; a.roundA = 0; a.roundB = 0; a.bTrans = 0; a.alpha = cScale;
        launch_gemm(a, 4);
    }

    // 4) softmax over 34304 segments of 268
    {
        int rows = cB * cN * cS;
        softmax_kernel<<<(rows + 7) / 8, 256>>>(P, rows);
    }

    // 5) U: NN over pre-rounded S, split-K x8 (K=1072 each), z = b*8+ks
    {
        GArgs a{};
        for (int z = 0; z < 32; ++z) {
            int b = z >> 3, ks = z & 7;
            a.Aarr[z] = P + (size_t)b * cN * TNK + (size_t)ks * 1072;
            a.Barr[z] = S + (size_t)b * SNE + (size_t)ks * 1072 * cE;
        }
        a.C = UP; a.M = cN; a.Nv = 1024; a.K = 1072;
        a.lda = TNK; a.ldb = cE; a.ldc = 1024; a.cStride = (long)NE;
        a.roundC = 0; a.roundA = 0; a.roundB = 0; a.bTrans = 1; a.alpha = 1.f;
        launch_gemm(a, 32);
        reduce_n<<<dim3((int)((NE4 + 255) / 256), 1, 4), 256>>>(
            (const float4*)UP, (float4*)U, NE4, NE4, 8, 1, 8 * NE4, NE4);
    }

    // 6) ms_b = U_b @ wv_b  (NN, raw wv_b rounded), split-K x8 (K=128), z=b*8+ks
    {
        GArgs a{};
        for (int z = 0; z < 32; ++z) {
            int b = z >> 3, ks = z & 7;
            a.Aarr[z] = U + (size_t)b * NE + ks * 128;
            a.Barr[z] = wv_b + (size_t)b * MM + (size_t)ks * 128 * 1024;
        }
        a.C = UP; a.M = cN; a.Nv = 1024; a.K = 128;
        a.lda = 1024; a.ldb = 1024; a.ldc = 1024; a.cStride = (long)NE;
        a.roundC = 0; a.roundA = 0; a.roundB = 1; a.bTrans = 1; a.alpha = 1.f;
        launch_gemm(a, 32);
        reduce_n<<<dim3((int)((NE4 + 255) / 256), 1, 4), 256>>>(
            (const float4*)UP, (float4*)MSp, NE4, NE4, 8, 1, 8 * NE4, NE4);
    }

    // 7) stage-2 scores: split-K x8 (K=128), partial-sum fused into softmax
    {
        GArgs a{};
        for (int z = 0; z < 8; ++z) { a.Aarr[z] = QH + 4 * NE + z * 128; a.Barr[z] = MSp + z * 128; }
        a.C = UP; a.M = cN; a.Nv = 4 * cN; a.K = 128;
        a.lda = 1024; a.ldb = 1024; a.ldc = (long)(4 * cN); a.cStride = (long)(cN * 4 * cN);
        a.roundC = 0; a.roundA = 0; a.roundB = 0; a.bTrans = 0; a.alpha = cScale;
        launch_gemm(a, 8);
        softmax_sum<<<(4 * cN + 7) / 8, 256>>>(UP, P2, 4 * cN, 8, (long)(cN * 4 * cN));
    }

    // 8) U2 = P2 @ ms  (NN, split-K x4 of total K=1072: 268 each, 16B-aligned)
    {
        GArgs a{};
        for (int z = 0; z < 4; ++z) { a.Aarr[z] = P2 + z * 268; a.Barr[z] = MSp + (size_t)z * 268 * 1024; }
        a.C = UP; a.M = cN; a.Nv = 1024; a.K = 268;
        a.lda = 4 * cN; a.ldb = 1024; a.ldc = 1024; a.cStride = (long)NE;
        a.roundC = 0; a.roundA = 0; a.roundB = 0; a.bTrans = 1; a.alpha = 1.f;
        launch_gemm(a, 4);
        reduce_n<<<(int)((NE4 + 255) / 256), 256>>>(
            (const float4*)UP, (float4*)U2, NE4, NE4, 4, 1, 0, 0);
    }

    // 9) out = U2 @ wv  (NN, raw wv rounded, split-K x8, K=128)
    {
        GArgs a{};
        for (int z = 0; z < 8; ++z) { a.Aarr[z] = U2 + z * 128; a.Barr[z] = wv + (size_t)z * 128 * 1024; }
        a.C = UP; a.M = cN; a.Nv = 1024; a.K = 128;
        a.lda = 1024; a.ldb = 1024; a.ldc = 1024; a.cStride = (long)NE;
        a.roundC = 0; a.roundA = 0; a.roundB = 1; a.bTrans = 1; a.alpha = 1.f;
        launch_gemm(a, 8);
        reduce_n<<<(int)((NE4 + 255) / 256), 256>>>(
            (const float4*)UP, (float4*)out, NE4, NE4, 8, 0, 0, 0);
    }
}